// round 11
// baseline (speedup 1.0000x reference)
#include <cuda_runtime.h>
#include <cstdint>
#include <math.h>

#define B_DIM  16384
#define ZD     128
#define HD     512
#define TSTEPS 32

// ---------------- device global scratch ----------------
__device__ __align__(16) float    g_W1c[HD * HD];               // W1[128:640,:] tf32 (ctxproj)
__device__ __align__(16) float    g_ctxr[(size_t)B_DIM * HD];   // ctx tf32 (ctxproj)
__device__ __align__(16) uint32_t g_ctxpb[(size_t)B_DIM * 256]; // ctxproj, packed bf16x2 pairs
__device__ __align__(16) uint32_t g_Wsl[32 * 2048];             // 32 weight slices, bf16x2 [16q][128n]
__device__ double g_sum;

// ---------------- helpers ----------------
__device__ __forceinline__ float rna(float x) {
    float r; asm("cvt.rna.tf32.f32 %0, %1;" : "=f"(r) : "f"(x)); return r;
}
__device__ __forceinline__ uint32_t packbf(float lo, float hi) {
    uint32_t r; asm("cvt.rn.bf16x2.f32 %0, %1, %2;" : "=r"(r) : "f"(hi), "f"(lo)); return r;
}
__device__ __forceinline__ float bflo(uint32_t u) { return __uint_as_float(u << 16); }
__device__ __forceinline__ float bfhi(uint32_t u) { return __uint_as_float(u & 0xFFFF0000u); }
__device__ __forceinline__ uint32_t sptr(const void* p) {
    return (uint32_t)__cvta_generic_to_shared(p);
}
__device__ __forceinline__ void cp16(uint32_t d, const void* s) {
    asm volatile("cp.async.cg.shared.global [%0], [%1], 16;" :: "r"(d), "l"(s));
}
#define CP_COMMIT() asm volatile("cp.async.commit_group;" ::: "memory")

#define MMA_TF32(acc, af, bf) \
    asm volatile("mma.sync.aligned.m16n8k8.row.col.f32.tf32.tf32.f32 " \
        "{%0,%1,%2,%3}, {%4,%5,%6,%7}, {%8,%9}, {%0,%1,%2,%3};" \
        : "+f"((acc)[0]), "+f"((acc)[1]), "+f"((acc)[2]), "+f"((acc)[3]) \
        : "r"((af)[0]), "r"((af)[1]), "r"((af)[2]), "r"((af)[3]), \
          "r"((bf)[0]), "r"((bf)[1]))

#define MMA_BF16(acc, af, b0, b1) \
    asm volatile("mma.sync.aligned.m16n8k16.row.col.f32.bf16.bf16.f32 " \
        "{%0,%1,%2,%3}, {%4,%5,%6,%7}, {%8,%9}, {%0,%1,%2,%3};" \
        : "+f"((acc)[0]), "+f"((acc)[1]), "+f"((acc)[2]), "+f"((acc)[3]) \
        : "r"((af)[0]), "r"((af)[1]), "r"((af)[2]), "r"((af)[3]), \
          "r"(b0), "r"(b1))

// ================= ctxproj tf32 GEMM (proven core, unchanged) =================
#define ASTR 20
#define BSTR 136

struct SmemT {
    float As[2][128][ASTR];
    float Bs[2][16][BSTR];
};

__device__ __forceinline__ void gemm_core(
    SmemT* s, const float* __restrict__ A, int lda,
    const float* __restrict__ Bm, int ldb, int K, float acc[2][8][4])
{
    const int tid = threadIdx.x;
    const int lane = tid & 31;
    const int w = tid >> 5, wm = w >> 1, wn = w & 1;
    const int nch = K / 16;

    #pragma unroll
    for (int i = 0; i < 2; i++) {
        int lin = tid + i * 256;
        int r = lin >> 2, kq = (lin & 3) * 4;
        cp16(sptr(&s->As[0][r][kq]), A + (size_t)r * lda + kq);
    }
    #pragma unroll
    for (int i = 0; i < 2; i++) {
        int lin = tid + i * 256;
        int kr = lin >> 5, nq = (lin & 31) * 4;
        cp16(sptr(&s->Bs[0][kr][nq]), Bm + (size_t)kr * ldb + nq);
    }
    CP_COMMIT();

    for (int c = 0; c < nch; c++) {
        const int buf = c & 1;
        if (c + 1 < nch) {
            const int k0 = (c + 1) * 16;
            #pragma unroll
            for (int i = 0; i < 2; i++) {
                int lin = tid + i * 256;
                int r = lin >> 2, kq = (lin & 3) * 4;
                cp16(sptr(&s->As[buf ^ 1][r][kq]), A + (size_t)r * lda + k0 + kq);
            }
            #pragma unroll
            for (int i = 0; i < 2; i++) {
                int lin = tid + i * 256;
                int kr = lin >> 5, nq = (lin & 31) * 4;
                cp16(sptr(&s->Bs[buf ^ 1][kr][nq]), Bm + (size_t)(k0 + kr) * ldb + nq);
            }
            CP_COMMIT();
            asm volatile("cp.async.wait_group 1;" ::: "memory");
        } else {
            asm volatile("cp.async.wait_group 0;" ::: "memory");
        }
        __syncthreads();

        #pragma unroll
        for (int kk = 0; kk < 16; kk += 8) {
            uint32_t af[2][4], bf[8][2];
            const int kb = kk + (lane & 3);
            #pragma unroll
            for (int mt = 0; mt < 2; mt++) {
                int r = wm * 32 + mt * 16 + (lane >> 2);
                af[mt][0] = __float_as_uint(s->As[buf][r][kb]);
                af[mt][1] = __float_as_uint(s->As[buf][r + 8][kb]);
                af[mt][2] = __float_as_uint(s->As[buf][r][kb + 4]);
                af[mt][3] = __float_as_uint(s->As[buf][r + 8][kb + 4]);
            }
            #pragma unroll
            for (int nt = 0; nt < 8; nt++) {
                int nn = wn * 64 + nt * 8 + (lane >> 2);
                bf[nt][0] = __float_as_uint(s->Bs[buf][kb][nn]);
                bf[nt][1] = __float_as_uint(s->Bs[buf][kb + 4][nn]);
            }
            #pragma unroll
            for (int mt = 0; mt < 2; mt++)
                #pragma unroll
                for (int nt = 0; nt < 8; nt++)
                    MMA_TF32(acc[mt][nt], af[mt], bf[nt]);
        }
        __syncthreads();
    }
}

__global__ void __launch_bounds__(256, 2) ctxproj_kernel(const float* __restrict__ b1)
{
    __shared__ SmemT s;
    float acc[2][8][4] = {};
    const int brow = blockIdx.y, bcol = blockIdx.x;
    gemm_core(&s, g_ctxr + (size_t)brow * 128 * HD, HD, g_W1c + bcol * 128, HD, HD, acc);

    const int lane = threadIdx.x & 31;
    const int w = threadIdx.x >> 5, wm = w >> 1, wn = w & 1;
    #pragma unroll
    for (int mt = 0; mt < 2; mt++) {
        #pragma unroll
        for (int nt = 0; nt < 8; nt++) {
            int r = brow * 128 + wm * 32 + mt * 16 + (lane >> 2);
            int c = bcol * 128 + wn * 64 + nt * 8 + 2 * (lane & 3);
            float2 bv = *reinterpret_cast<const float2*>(&b1[c]);
            g_ctxpb[(size_t)r * 256 + (c >> 1)] =
                packbf(acc[mt][nt][0] + bv.x, acc[mt][nt][1] + bv.y);
            g_ctxpb[(size_t)(r + 8) * 256 + (c >> 1)] =
                packbf(acc[mt][nt][2] + bv.x, acc[mt][nt][3] + bv.y);
        }
    }
}

// ================= persistent bf16 step kernel =================
// 8 warps (4m x 2n), warp tile 32x64, CTA tile 128 rows.
// Weight ring: 8 slots = 2 groups of 4 slices; 1 barrier + 1 wait per group.
// Epilogue memory latency hidden by register prefetch under MMA groups.
struct PS {
    float    zf[128][130];    // fp32 z state           66560 B
    uint32_t zb[128][68];     // bf16x2 z pairs         34816 B
    uint32_t hb[128][68];     // bf16x2 h chunk pairs   34816 B
    uint32_t wb[8][16][136];  // weight slice ring      69632 B
};
#define PS_SZ ((int)sizeof(PS))

extern __shared__ char dynsm[];

__device__ __forceinline__ void mma_slice(
    float acc[2][8][4], const uint32_t (&A)[128][68], int qb,
    const uint32_t (&Bm)[16][136], int lane, int wm, int wn)
{
    #pragma unroll
    for (int kt = 0; kt < 2; kt++) {
        const int qa = qb + kt * 8 + (lane & 3);
        uint32_t af[2][4];
        #pragma unroll
        for (int mt = 0; mt < 2; mt++) {
            int r = wm * 32 + mt * 16 + (lane >> 2);
            af[mt][0] = A[r][qa];
            af[mt][1] = A[r + 8][qa];
            af[mt][2] = A[r][qa + 4];
            af[mt][3] = A[r + 8][qa + 4];
        }
        const int kq = kt * 8 + (lane & 3);
        #pragma unroll
        for (int nt = 0; nt < 8; nt++) {
            int nn = wn * 64 + nt * 8 + (lane >> 2);
            uint32_t b0 = Bm[kq][nn];
            uint32_t b1 = Bm[kq + 4][nn];
            #pragma unroll
            for (int mt = 0; mt < 2; mt++)
                MMA_BF16(acc[mt][nt], af[mt], b0, b1);
        }
    }
}

__global__ void __launch_bounds__(256, 1) step_kernel(
    const float* __restrict__ eps0, const float* __restrict__ eps,
    const float* __restrict__ beta, const float* __restrict__ sigma0,
    const float* __restrict__ b2,   const float* __restrict__ temb,
    const float* __restrict__ tmu)
{
    PS* s = (PS*)dynsm;
    const int tid = threadIdx.x, lane = tid & 31, w = tid >> 5;
    const int wm = w >> 1, wn = w & 1;
    const int grow0 = blockIdx.x * 128;

    const float s0 = sigma0[0];
    const float lg = logf(s0);
    const float dt = 1.0f / TSTEPS;
    double ssum = 0.0;

    // ---- init z (fp32 + bf16 copy) + prior-correction term ----
    {
        float local = 0.f;
        #pragma unroll
        for (int i = 0; i < 16; i++) {
            int lin = (tid + i * 256) * 4;
            int row = lin >> 7, col = lin & 127;
            float4 e = *reinterpret_cast<const float4*>(&eps0[(size_t)(grow0 + row) * ZD + col]);
            float z0 = s0 * e.x, z1 = s0 * e.y, z2 = s0 * e.z, z3 = s0 * e.w;
            s->zf[row][col + 0] = z0; s->zf[row][col + 1] = z1;
            s->zf[row][col + 2] = z2; s->zf[row][col + 3] = z3;
            s->zb[row][(col >> 1) + 0] = packbf(z0, z1);
            s->zb[row][(col >> 1) + 1] = packbf(z2, z3);
            local += 0.5f * (e.x * e.x + e.y * e.y + e.z * e.z + e.w * e.w) + 4.f * lg;
        }
        ssum += (double)local;
    }

// issue one group (4 slices = 32KB) into ring half (gv&1)
#define ISSUE_GROUP(gv) do { \
    const uint32_t* _src = g_Wsl + ((gv) & 7) * 8192; \
    const int _slot0 = ((gv) & 1) * 4; \
    _Pragma("unroll") \
    for (int _i = 0; _i < 8; _i++) { \
        int _j = tid + _i * 256; \
        int _sl = _j >> 9, _rem = _j & 511; \
        cp16(sptr(&s->wb[_slot0 + _sl][_rem >> 5][(_rem & 31) * 4]), \
             _src + _sl * 2048 + _rem * 4); \
    } \
    CP_COMMIT(); \
} while (0)

// wait for the group we're about to consume (issued one group ago), barrier
#define GROUP_SYNC() do { \
    asm volatile("cp.async.wait_group 0;" ::: "memory"); \
    __syncthreads(); \
} while (0)

    // prologue: issue group 0
    ISSUE_GROUP(0);

    int g = 0;
    for (int t = 0; t < TSTEPS; t++) {
        const float beta_f = __ldg(&beta[t]);
        const float beta_b = __ldg(&beta[(t + TSTEPS - 1) % TSTEPS]);
        const float sig_f = sqrtf(2.0f * beta_f * dt) * s0;
        const float sig_b = sqrtf(2.0f * beta_b * dt) * s0;
        const float inv_sb = 1.0f / sig_b;
        const float logdiff = logf(sig_f) - logf(sig_b);
        const float* eps_t = eps + ((size_t)t * B_DIM + grow0) * ZD;

        float accu[2][8][4] = {};
        float2 evr[8][2][2];   // eps prefetch (filled during last MMA2 group)

        #pragma unroll
        for (int c = 0; c < 4; c++) {
            // ---- MMA1 group: acch = z @ W1a[:, c] ----
            float acch[2][8][4] = {};
            GROUP_SYNC();
            ISSUE_GROUP(g + 1);
            // prefetch ctxpb for this chunk (consumed in epilogue1; hidden under MMAs)
            uint32_t cpr[8][2][2];
            #pragma unroll
            for (int nt = 0; nt < 8; nt++) {
                int lq = wn * 32 + nt * 4 + (lane & 3);
                #pragma unroll
                for (int mt = 0; mt < 2; mt++) {
                    int r = wm * 32 + mt * 16 + (lane >> 2);
                    cpr[nt][mt][0] = __ldg(&g_ctxpb[(size_t)(grow0 + r) * 256 + c * 64 + lq]);
                    cpr[nt][mt][1] = __ldg(&g_ctxpb[(size_t)(grow0 + r + 8) * 256 + c * 64 + lq]);
                }
            }
            {
                const int slot0 = (g & 1) * 4;
                #pragma unroll
                for (int kc = 0; kc < 4; kc++)
                    mma_slice(acch, s->zb, kc * 16, s->wb[slot0 + kc], lane, wm, wn);
            }
            g++;
            // ---- epilogue1: h = bf16(relu(acch + ctxp + te)) -> hb ----
            #pragma unroll
            for (int nt = 0; nt < 8; nt++) {
                int gc = c * 128 + wn * 64 + nt * 8 + 2 * (lane & 3);
                float2 te = *reinterpret_cast<const float2*>(&temb[(size_t)t * HD + gc]);
                int lq = wn * 32 + nt * 4 + (lane & 3);
                #pragma unroll
                for (int mt = 0; mt < 2; mt++) {
                    int r = wm * 32 + mt * 16 + (lane >> 2);
                    #pragma unroll
                    for (int hf = 0; hf < 2; hf++) {
                        int rr = r + 8 * hf;
                        uint32_t cpv = cpr[nt][mt][hf];
                        float v0 = acch[mt][nt][hf * 2 + 0] + bflo(cpv) + te.x;
                        float v1 = acch[mt][nt][hf * 2 + 1] + bfhi(cpv) + te.y;
                        s->hb[rr][lq] = packbf(fmaxf(v0, 0.f), fmaxf(v1, 0.f));
                    }
                }
            }
            // ---- MMA2 group: accu += h @ W2[c, :] ----
            GROUP_SYNC();
            ISSUE_GROUP(g + 1);
            if (c == 3) {
                // prefetch eps for the update epilogue (hidden under MMAs)
                #pragma unroll
                for (int nt = 0; nt < 8; nt++) {
                    int cc = wn * 64 + nt * 8 + 2 * (lane & 3);
                    #pragma unroll
                    for (int mt = 0; mt < 2; mt++) {
                        int r = wm * 32 + mt * 16 + (lane >> 2);
                        evr[nt][mt][0] = *reinterpret_cast<const float2*>(
                            &eps_t[(size_t)r * ZD + cc]);
                        evr[nt][mt][1] = *reinterpret_cast<const float2*>(
                            &eps_t[(size_t)(r + 8) * ZD + cc]);
                    }
                }
            }
            {
                const int slot0 = (g & 1) * 4;
                #pragma unroll
                for (int kc = 0; kc < 4; kc++)
                    mma_slice(accu, s->hb, kc * 16, s->wb[slot0 + kc], lane, wm, wn);
            }
            g++;
        }

        // ---- update epilogue ----
        float local = 0.f;
        #pragma unroll
        for (int nt = 0; nt < 8; nt++) {
            int cc = wn * 64 + nt * 8 + 2 * (lane & 3);
            float2 bv = *reinterpret_cast<const float2*>(&b2[cc]);
            #pragma unroll
            for (int mt = 0; mt < 2; mt++) {
                int r = wm * 32 + mt * 16 + (lane >> 2);
                #pragma unroll
                for (int hf = 0; hf < 2; hf++) {
                    int rr = r + 8 * hf;
                    float2 zp = *reinterpret_cast<const float2*>(&s->zf[rr][cc]);
                    float2 ev = evr[nt][mt][hf];
                    float u0 = accu[mt][nt][hf * 2 + 0] + bv.x;
                    float u1 = accu[mt][nt][hf * 2 + 1] + bv.y;
                    float mu0 = zp.x + (beta_f * zp.x + u0) * dt;
                    float mu1 = zp.y + (beta_f * zp.y + u1) * dt;
                    float zn0 = fmaf(sig_f, ev.x, mu0);
                    float zn1 = fmaf(sig_f, ev.y, mu1);
                    float mb0 = zn0 - beta_b * zn0 * dt;
                    float mb1 = zn1 - beta_b * zn1 * dt;
                    float a10 = (zp.x - mb0) * inv_sb;
                    float a11 = (zp.y - mb1) * inv_sb;
                    local += 0.5f * (ev.x * ev.x - a10 * a10) + logdiff;
                    local += 0.5f * (ev.y * ev.y - a11 * a11) + logdiff;
                    if (t == TSTEPS - 1) {
                        float2 tm = *reinterpret_cast<const float2*>(
                            &tmu[(size_t)(grow0 + rr) * ZD + cc]);
                        float d0 = zn0 - tm.x, d1 = zn1 - tm.y;
                        local -= 0.5f * (d0 * d0 + d1 * d1);
                    }
                    float2 zo = { zn0, zn1 };
                    *reinterpret_cast<float2*>(&s->zf[rr][cc]) = zo;
                    s->zb[rr][cc >> 1] = packbf(zn0, zn1);
                }
            }
        }
        ssum += (double)local;
    }

    // ---- reduce ----
    asm volatile("cp.async.wait_group 0;" ::: "memory");
    __syncthreads();
    double* red = reinterpret_cast<double*>(&s->wb[0][0][0]);
    red[tid] = ssum;
    __syncthreads();
    for (int st = 128; st > 0; st >>= 1) {
        if (tid < st) red[tid] += red[tid + st];
        __syncthreads();
    }
    if (tid == 0) atomicAdd(&g_sum, red[0]);
}

// ---------------- prep / finalize ----------------
__global__ void prep_w1c(const float* __restrict__ W1)
{
    const int N = HD * HD;
    for (int i = blockIdx.x * blockDim.x + threadIdx.x; i < N; i += gridDim.x * blockDim.x)
        g_W1c[i] = rna(W1[ZD * HD + i]);
}
__global__ void prep_ctx(const float* __restrict__ ctx)
{
    const size_t N = (size_t)B_DIM * HD;
    size_t i0 = (size_t)blockIdx.x * blockDim.x + threadIdx.x;
    if (i0 == 0) g_sum = 0.0;
    for (size_t i = i0; i < N; i += (size_t)gridDim.x * blockDim.x)
        g_ctxr[i] = rna(ctx[i]);
}
// build packed bf16 weight slices: slice si: c=si>>3, ph=(si>>2)&1, kc=si&3
// slice layout [16q][128n]; word idx = q*128 + n
__global__ void prep_slices(const float* __restrict__ W1, const float* __restrict__ W2)
{
    int idx = blockIdx.x * blockDim.x + threadIdx.x;
    if (idx >= 32 * 2048) return;
    int si = idx >> 11, rem = idx & 2047;
    int q = rem >> 7, n = rem & 127;
    int c = si >> 3, ph = (si >> 2) & 1, kc = si & 3;
    float v0, v1;
    if (!ph) {
        int k0 = kc * 32 + 2 * q;
        v0 = W1[(size_t)k0 * HD + c * 128 + n];
        v1 = W1[(size_t)(k0 + 1) * HD + c * 128 + n];
    } else {
        int k0 = c * 128 + kc * 32 + 2 * q;
        v0 = W2[(size_t)k0 * ZD + n];
        v1 = W2[(size_t)(k0 + 1) * ZD + n];
    }
    g_Wsl[idx] = packbf(v0, v1);
}
__global__ void write_out(float* __restrict__ out)
{
    out[0] = (float)(g_sum / (double)B_DIM);
}

// ---------------- host launcher ----------------
extern "C" void kernel_launch(void* const* d_in, const int* in_sizes, int n_in,
                              void* d_out, int out_size)
{
    (void)in_sizes; (void)n_in; (void)out_size;
    const float* ctx    = (const float*)d_in[0];
    const float* eps0   = (const float*)d_in[1];
    const float* eps    = (const float*)d_in[2];
    const float* beta   = (const float*)d_in[3];
    const float* sigma0 = (const float*)d_in[4];
    const float* W1     = (const float*)d_in[5];
    const float* b1     = (const float*)d_in[6];
    const float* W2     = (const float*)d_in[7];
    const float* b2     = (const float*)d_in[8];
    const float* temb   = (const float*)d_in[9];
    const float* tmu    = (const float*)d_in[10];
    float* out = (float*)d_out;

    cudaFuncSetAttribute(step_kernel, cudaFuncAttributeMaxDynamicSharedMemorySize, PS_SZ);

    prep_w1c<<<256, 256>>>(W1);
    prep_ctx<<<2048, 256>>>(ctx);
    prep_slices<<<256, 256>>>(W1, W2);
    ctxproj_kernel<<<dim3(4, 128), 256>>>(b1);
    step_kernel<<<128, 256, PS_SZ>>>(eps0, eps, beta, sigma0, b2, temb, tmu);
    write_out<<<1, 1>>>(out);
}

// round 12
// speedup vs baseline: 1.0591x; 1.0591x over previous
#include <cuda_runtime.h>
#include <cstdint>
#include <math.h>

#define B_DIM  16384
#define ZD     128
#define HD     512
#define TSTEPS 32

// ---------------- device global scratch ----------------
__device__ __align__(16) float    g_W1c[HD * HD];               // W1[128:640,:] tf32 (ctxproj)
__device__ __align__(16) float    g_ctxr[(size_t)B_DIM * HD];   // ctx tf32 (ctxproj)
__device__ __align__(16) uint32_t g_ctxpb[(size_t)B_DIM * 256]; // ctxproj, packed bf16x2 pairs
__device__ __align__(16) uint32_t g_Wsl[32 * 2048];             // 32 weight slices, bf16x2 [16q][128n]
__device__ double g_sum;

// ---------------- helpers ----------------
__device__ __forceinline__ float rna(float x) {
    float r; asm("cvt.rna.tf32.f32 %0, %1;" : "=f"(r) : "f"(x)); return r;
}
__device__ __forceinline__ uint32_t packbf(float lo, float hi) {
    uint32_t r; asm("cvt.rn.bf16x2.f32 %0, %1, %2;" : "=r"(r) : "f"(hi), "f"(lo)); return r;
}
__device__ __forceinline__ float bflo(uint32_t u) { return __uint_as_float(u << 16); }
__device__ __forceinline__ float bfhi(uint32_t u) { return __uint_as_float(u & 0xFFFF0000u); }
__device__ __forceinline__ uint32_t sptr(const void* p) {
    return (uint32_t)__cvta_generic_to_shared(p);
}
__device__ __forceinline__ void cp16(uint32_t d, const void* s) {
    asm volatile("cp.async.cg.shared.global [%0], [%1], 16;" :: "r"(d), "l"(s));
}
#define CP_COMMIT() asm volatile("cp.async.commit_group;" ::: "memory")

#define MMA_TF32(acc, af, bf) \
    asm volatile("mma.sync.aligned.m16n8k8.row.col.f32.tf32.tf32.f32 " \
        "{%0,%1,%2,%3}, {%4,%5,%6,%7}, {%8,%9}, {%0,%1,%2,%3};" \
        : "+f"((acc)[0]), "+f"((acc)[1]), "+f"((acc)[2]), "+f"((acc)[3]) \
        : "r"((af)[0]), "r"((af)[1]), "r"((af)[2]), "r"((af)[3]), \
          "r"((bf)[0]), "r"((bf)[1]))

#define MMA_BF16(acc, af, b0, b1) \
    asm volatile("mma.sync.aligned.m16n8k16.row.col.f32.bf16.bf16.f32 " \
        "{%0,%1,%2,%3}, {%4,%5,%6,%7}, {%8,%9}, {%0,%1,%2,%3};" \
        : "+f"((acc)[0]), "+f"((acc)[1]), "+f"((acc)[2]), "+f"((acc)[3]) \
        : "r"((af)[0]), "r"((af)[1]), "r"((af)[2]), "r"((af)[3]), \
          "r"(b0), "r"(b1))

// ================= ctxproj tf32 GEMM (proven core, unchanged) =================
#define ASTR 20
#define BSTR 136

struct SmemT {
    float As[2][128][ASTR];
    float Bs[2][16][BSTR];
};

__device__ __forceinline__ void gemm_core(
    SmemT* s, const float* __restrict__ A, int lda,
    const float* __restrict__ Bm, int ldb, int K, float acc[2][8][4])
{
    const int tid = threadIdx.x;
    const int lane = tid & 31;
    const int w = tid >> 5, wm = w >> 1, wn = w & 1;
    const int nch = K / 16;

    #pragma unroll
    for (int i = 0; i < 2; i++) {
        int lin = tid + i * 256;
        int r = lin >> 2, kq = (lin & 3) * 4;
        cp16(sptr(&s->As[0][r][kq]), A + (size_t)r * lda + kq);
    }
    #pragma unroll
    for (int i = 0; i < 2; i++) {
        int lin = tid + i * 256;
        int kr = lin >> 5, nq = (lin & 31) * 4;
        cp16(sptr(&s->Bs[0][kr][nq]), Bm + (size_t)kr * ldb + nq);
    }
    CP_COMMIT();

    for (int c = 0; c < nch; c++) {
        const int buf = c & 1;
        if (c + 1 < nch) {
            const int k0 = (c + 1) * 16;
            #pragma unroll
            for (int i = 0; i < 2; i++) {
                int lin = tid + i * 256;
                int r = lin >> 2, kq = (lin & 3) * 4;
                cp16(sptr(&s->As[buf ^ 1][r][kq]), A + (size_t)r * lda + k0 + kq);
            }
            #pragma unroll
            for (int i = 0; i < 2; i++) {
                int lin = tid + i * 256;
                int kr = lin >> 5, nq = (lin & 31) * 4;
                cp16(sptr(&s->Bs[buf ^ 1][kr][nq]), Bm + (size_t)(k0 + kr) * ldb + nq);
            }
            CP_COMMIT();
            asm volatile("cp.async.wait_group 1;" ::: "memory");
        } else {
            asm volatile("cp.async.wait_group 0;" ::: "memory");
        }
        __syncthreads();

        #pragma unroll
        for (int kk = 0; kk < 16; kk += 8) {
            uint32_t af[2][4], bf[8][2];
            const int kb = kk + (lane & 3);
            #pragma unroll
            for (int mt = 0; mt < 2; mt++) {
                int r = wm * 32 + mt * 16 + (lane >> 2);
                af[mt][0] = __float_as_uint(s->As[buf][r][kb]);
                af[mt][1] = __float_as_uint(s->As[buf][r + 8][kb]);
                af[mt][2] = __float_as_uint(s->As[buf][r][kb + 4]);
                af[mt][3] = __float_as_uint(s->As[buf][r + 8][kb + 4]);
            }
            #pragma unroll
            for (int nt = 0; nt < 8; nt++) {
                int nn = wn * 64 + nt * 8 + (lane >> 2);
                bf[nt][0] = __float_as_uint(s->Bs[buf][kb][nn]);
                bf[nt][1] = __float_as_uint(s->Bs[buf][kb + 4][nn]);
            }
            #pragma unroll
            for (int mt = 0; mt < 2; mt++)
                #pragma unroll
                for (int nt = 0; nt < 8; nt++)
                    MMA_TF32(acc[mt][nt], af[mt], bf[nt]);
        }
        __syncthreads();
    }
}

__global__ void __launch_bounds__(256, 2) ctxproj_kernel(const float* __restrict__ b1)
{
    __shared__ SmemT s;
    float acc[2][8][4] = {};
    const int brow = blockIdx.y, bcol = blockIdx.x;
    gemm_core(&s, g_ctxr + (size_t)brow * 128 * HD, HD, g_W1c + bcol * 128, HD, HD, acc);

    const int lane = threadIdx.x & 31;
    const int w = threadIdx.x >> 5, wm = w >> 1, wn = w & 1;
    #pragma unroll
    for (int mt = 0; mt < 2; mt++) {
        #pragma unroll
        for (int nt = 0; nt < 8; nt++) {
            int r = brow * 128 + wm * 32 + mt * 16 + (lane >> 2);
            int c = bcol * 128 + wn * 64 + nt * 8 + 2 * (lane & 3);
            float2 bv = *reinterpret_cast<const float2*>(&b1[c]);
            g_ctxpb[(size_t)r * 256 + (c >> 1)] =
                packbf(acc[mt][nt][0] + bv.x, acc[mt][nt][1] + bv.y);
            g_ctxpb[(size_t)(r + 8) * 256 + (c >> 1)] =
                packbf(acc[mt][nt][2] + bv.x, acc[mt][nt][3] + bv.y);
        }
    }
}

// ================= persistent bf16 step kernel =================
// 64-row CTAs, 2 CTAs/SM for hardware-scheduled MMA/epilogue overlap.
// 4 warps (2m x 2n), warp tile 32x64.
// Weight ring: 4 slots = 2 groups of 2 slices; 1 barrier + 1 wait per group.
struct PS {
    float    zf[64][130];     // fp32 z state           33280 B
    uint32_t zb[64][68];      // bf16x2 z pairs         17408 B
    uint32_t hb[64][68];      // bf16x2 h chunk pairs   17408 B
    uint32_t wb[4][16][136];  // weight slice ring      34816 B
};
#define PS_SZ ((int)sizeof(PS))   // 102912 B -> two CTAs fit in 227KB

extern __shared__ char dynsm[];

__device__ __forceinline__ void mma_slice(
    float acc[2][8][4], const uint32_t (&A)[64][68], int qb,
    const uint32_t (&Bm)[16][136], int lane, int wm, int wn)
{
    #pragma unroll
    for (int kt = 0; kt < 2; kt++) {
        const int qa = qb + kt * 8 + (lane & 3);
        uint32_t af[2][4];
        #pragma unroll
        for (int mt = 0; mt < 2; mt++) {
            int r = wm * 32 + mt * 16 + (lane >> 2);
            af[mt][0] = A[r][qa];
            af[mt][1] = A[r + 8][qa];
            af[mt][2] = A[r][qa + 4];
            af[mt][3] = A[r + 8][qa + 4];
        }
        const int kq = kt * 8 + (lane & 3);
        #pragma unroll
        for (int nt = 0; nt < 8; nt++) {
            int nn = wn * 64 + nt * 8 + (lane >> 2);
            uint32_t b0 = Bm[kq][nn];
            uint32_t b1 = Bm[kq + 4][nn];
            #pragma unroll
            for (int mt = 0; mt < 2; mt++)
                MMA_BF16(acc[mt][nt], af[mt], b0, b1);
        }
    }
}

__global__ void __launch_bounds__(128, 2) step_kernel(
    const float* __restrict__ eps0, const float* __restrict__ eps,
    const float* __restrict__ beta, const float* __restrict__ sigma0,
    const float* __restrict__ b2,   const float* __restrict__ temb,
    const float* __restrict__ tmu)
{
    PS* s = (PS*)dynsm;
    const int tid = threadIdx.x, lane = tid & 31, w = tid >> 5;
    const int wm = w >> 1, wn = w & 1;
    const int grow0 = blockIdx.x * 64;

    const float s0 = sigma0[0];
    const float lg = logf(s0);
    const float dt = 1.0f / TSTEPS;
    double ssum = 0.0;

    // ---- init z (fp32 + bf16 copy) + prior-correction term ----
    {
        float local = 0.f;
        #pragma unroll
        for (int i = 0; i < 16; i++) {
            int lin = (tid + i * 128) * 4;
            int row = lin >> 7, col = lin & 127;
            float4 e = *reinterpret_cast<const float4*>(&eps0[(size_t)(grow0 + row) * ZD + col]);
            float z0 = s0 * e.x, z1 = s0 * e.y, z2 = s0 * e.z, z3 = s0 * e.w;
            s->zf[row][col + 0] = z0; s->zf[row][col + 1] = z1;
            s->zf[row][col + 2] = z2; s->zf[row][col + 3] = z3;
            s->zb[row][(col >> 1) + 0] = packbf(z0, z1);
            s->zb[row][(col >> 1) + 1] = packbf(z2, z3);
            local += 0.5f * (e.x * e.x + e.y * e.y + e.z * e.z + e.w * e.w) + 4.f * lg;
        }
        ssum += (double)local;
    }

// issue one group (2 slices = 16KB) into ring half (gv&1)
#define ISSUE_GROUP(gv) do { \
    const uint32_t* _src = g_Wsl + (((gv) & 15) * 2) * 2048; \
    const int _slot0 = ((gv) & 1) * 2; \
    _Pragma("unroll") \
    for (int _i = 0; _i < 8; _i++) { \
        int _j = tid + _i * 128; \
        int _sl = _j >> 9, _rem = _j & 511; \
        cp16(sptr(&s->wb[_slot0 + _sl][_rem >> 5][(_rem & 31) * 4]), \
             _src + _sl * 2048 + _rem * 4); \
    } \
    CP_COMMIT(); \
} while (0)

#define GROUP_SYNC() do { \
    asm volatile("cp.async.wait_group 0;" ::: "memory"); \
    __syncthreads(); \
} while (0)

    // prologue: issue group 0
    ISSUE_GROUP(0);

    int g = 0;
    for (int t = 0; t < TSTEPS; t++) {
        const float beta_f = __ldg(&beta[t]);
        const float beta_b = __ldg(&beta[(t + TSTEPS - 1) % TSTEPS]);
        const float sig_f = sqrtf(2.0f * beta_f * dt) * s0;
        const float sig_b = sqrtf(2.0f * beta_b * dt) * s0;
        const float inv_sb = 1.0f / sig_b;
        const float logdiff = logf(sig_f) - logf(sig_b);
        const float* eps_t = eps + ((size_t)t * B_DIM + grow0) * ZD;

        float accu[2][8][4] = {};

        for (int c = 0; c < 4; c++) {
            // ---- MMA1: acch = z @ W1a[:, c]  (2 groups of 2 slices) ----
            float acch[2][8][4] = {};
            #pragma unroll
            for (int half = 0; half < 2; half++) {
                GROUP_SYNC();
                ISSUE_GROUP(g + 1);
                const int slot0 = (g & 1) * 2;
                mma_slice(acch, s->zb, (half * 2 + 0) * 16, s->wb[slot0 + 0], lane, wm, wn);
                mma_slice(acch, s->zb, (half * 2 + 1) * 16, s->wb[slot0 + 1], lane, wm, wn);
                g++;
            }
            // ---- epilogue1: h = bf16(relu(acch + ctxp + te)) -> hb ----
            #pragma unroll
            for (int nt = 0; nt < 8; nt++) {
                int gc = c * 128 + wn * 64 + nt * 8 + 2 * (lane & 3);
                float2 te = *reinterpret_cast<const float2*>(&temb[(size_t)t * HD + gc]);
                int lq = wn * 32 + nt * 4 + (lane & 3);
                #pragma unroll
                for (int mt = 0; mt < 2; mt++) {
                    int r = wm * 32 + mt * 16 + (lane >> 2);
                    #pragma unroll
                    for (int hf = 0; hf < 2; hf++) {
                        int rr = r + 8 * hf;
                        uint32_t cpv = __ldg(&g_ctxpb[(size_t)(grow0 + rr) * 256 + c * 64 + lq]);
                        float v0 = acch[mt][nt][hf * 2 + 0] + bflo(cpv) + te.x;
                        float v1 = acch[mt][nt][hf * 2 + 1] + bfhi(cpv) + te.y;
                        s->hb[rr][lq] = packbf(fmaxf(v0, 0.f), fmaxf(v1, 0.f));
                    }
                }
            }
            // ---- MMA2: accu += h @ W2[c, :]  (2 groups of 2 slices) ----
            #pragma unroll
            for (int half = 0; half < 2; half++) {
                GROUP_SYNC();
                ISSUE_GROUP(g + 1);
                const int slot0 = (g & 1) * 2;
                mma_slice(accu, s->hb, (half * 2 + 0) * 16, s->wb[slot0 + 0], lane, wm, wn);
                mma_slice(accu, s->hb, (half * 2 + 1) * 16, s->wb[slot0 + 1], lane, wm, wn);
                g++;
            }
        }

        // ---- update epilogue ----
        float local = 0.f;
        #pragma unroll
        for (int nt = 0; nt < 8; nt++) {
            int cc = wn * 64 + nt * 8 + 2 * (lane & 3);
            float2 bv = *reinterpret_cast<const float2*>(&b2[cc]);
            #pragma unroll
            for (int mt = 0; mt < 2; mt++) {
                int r = wm * 32 + mt * 16 + (lane >> 2);
                #pragma unroll
                for (int hf = 0; hf < 2; hf++) {
                    int rr = r + 8 * hf;
                    float2 zp = *reinterpret_cast<const float2*>(&s->zf[rr][cc]);
                    float2 ev = *reinterpret_cast<const float2*>(&eps_t[(size_t)rr * ZD + cc]);
                    float u0 = accu[mt][nt][hf * 2 + 0] + bv.x;
                    float u1 = accu[mt][nt][hf * 2 + 1] + bv.y;
                    float mu0 = zp.x + (beta_f * zp.x + u0) * dt;
                    float mu1 = zp.y + (beta_f * zp.y + u1) * dt;
                    float zn0 = fmaf(sig_f, ev.x, mu0);
                    float zn1 = fmaf(sig_f, ev.y, mu1);
                    float mb0 = zn0 - beta_b * zn0 * dt;
                    float mb1 = zn1 - beta_b * zn1 * dt;
                    float a10 = (zp.x - mb0) * inv_sb;
                    float a11 = (zp.y - mb1) * inv_sb;
                    local += 0.5f * (ev.x * ev.x - a10 * a10) + logdiff;
                    local += 0.5f * (ev.y * ev.y - a11 * a11) + logdiff;
                    if (t == TSTEPS - 1) {
                        float2 tm = *reinterpret_cast<const float2*>(
                            &tmu[(size_t)(grow0 + rr) * ZD + cc]);
                        float d0 = zn0 - tm.x, d1 = zn1 - tm.y;
                        local -= 0.5f * (d0 * d0 + d1 * d1);
                    }
                    float2 zo = { zn0, zn1 };
                    *reinterpret_cast<float2*>(&s->zf[rr][cc]) = zo;
                    s->zb[rr][cc >> 1] = packbf(zn0, zn1);
                }
            }
        }
        ssum += (double)local;
    }

    // ---- reduce ----
    asm volatile("cp.async.wait_group 0;" ::: "memory");
    __syncthreads();
    double* red = reinterpret_cast<double*>(&s->wb[0][0][0]);
    red[tid] = ssum;
    __syncthreads();
    for (int st = 64; st > 0; st >>= 1) {
        if (tid < st) red[tid] += red[tid + st];
        __syncthreads();
    }
    if (tid == 0) atomicAdd(&g_sum, red[0]);
}

// ---------------- prep / finalize ----------------
__global__ void prep_w1c(const float* __restrict__ W1)
{
    const int N = HD * HD;
    for (int i = blockIdx.x * blockDim.x + threadIdx.x; i < N; i += gridDim.x * blockDim.x)
        g_W1c[i] = rna(W1[ZD * HD + i]);
}
__global__ void prep_ctx(const float* __restrict__ ctx)
{
    const size_t N = (size_t)B_DIM * HD;
    size_t i0 = (size_t)blockIdx.x * blockDim.x + threadIdx.x;
    if (i0 == 0) g_sum = 0.0;
    for (size_t i = i0; i < N; i += (size_t)gridDim.x * blockDim.x)
        g_ctxr[i] = rna(ctx[i]);
}
// build packed bf16 weight slices: slice si: c=si>>3, ph=(si>>2)&1, kc=si&3
// slice layout [16q][128n]; word idx = q*128 + n
__global__ void prep_slices(const float* __restrict__ W1, const float* __restrict__ W2)
{
    int idx = blockIdx.x * blockDim.x + threadIdx.x;
    if (idx >= 32 * 2048) return;
    int si = idx >> 11, rem = idx & 2047;
    int q = rem >> 7, n = rem & 127;
    int c = si >> 3, ph = (si >> 2) & 1, kc = si & 3;
    float v0, v1;
    if (!ph) {
        int k0 = kc * 32 + 2 * q;
        v0 = W1[(size_t)k0 * HD + c * 128 + n];
        v1 = W1[(size_t)(k0 + 1) * HD + c * 128 + n];
    } else {
        int k0 = c * 128 + kc * 32 + 2 * q;
        v0 = W2[(size_t)k0 * ZD + n];
        v1 = W2[(size_t)(k0 + 1) * ZD + n];
    }
    g_Wsl[idx] = packbf(v0, v1);
}
__global__ void write_out(float* __restrict__ out)
{
    out[0] = (float)(g_sum / (double)B_DIM);
}

// ---------------- host launcher ----------------
extern "C" void kernel_launch(void* const* d_in, const int* in_sizes, int n_in,
                              void* d_out, int out_size)
{
    (void)in_sizes; (void)n_in; (void)out_size;
    const float* ctx    = (const float*)d_in[0];
    const float* eps0   = (const float*)d_in[1];
    const float* eps    = (const float*)d_in[2];
    const float* beta   = (const float*)d_in[3];
    const float* sigma0 = (const float*)d_in[4];
    const float* W1     = (const float*)d_in[5];
    const float* b1     = (const float*)d_in[6];
    const float* W2     = (const float*)d_in[7];
    const float* b2     = (const float*)d_in[8];
    const float* temb   = (const float*)d_in[9];
    const float* tmu    = (const float*)d_in[10];
    float* out = (float*)d_out;

    cudaFuncSetAttribute(step_kernel, cudaFuncAttributeMaxDynamicSharedMemorySize, PS_SZ);

    prep_w1c<<<256, 256>>>(W1);
    prep_ctx<<<2048, 256>>>(ctx);
    prep_slices<<<256, 256>>>(W1, W2);
    ctxproj_kernel<<<dim3(4, 128), 256>>>(b1);
    step_kernel<<<256, 128, PS_SZ>>>(eps0, eps, beta, sigma0, b2, temb, tmu);
    write_out<<<1, 1>>>(out);
}

// round 13
// speedup vs baseline: 1.1204x; 1.0579x over previous
#include <cuda_runtime.h>
#include <cstdint>
#include <math.h>

#define B_DIM  16384
#define ZD     128
#define HD     512
#define TSTEPS 32

// ---------------- device global scratch ----------------
__device__ __align__(16) uint32_t g_ctxb[(size_t)B_DIM * 256]; // ctx packed bf16x2 pairs
__device__ __align__(16) uint32_t g_W1cb[64 * 2048];           // W1[128:640,:] bf16 slices [16q][128n]
__device__ __align__(16) uint32_t g_ctxpb[(size_t)B_DIM * 256]; // ctxproj, packed bf16x2 pairs
__device__ __align__(16) uint32_t g_Wsl[32 * 2048];             // 32 loop weight slices [16q][128n]
__device__ double g_sum;

// ---------------- helpers ----------------
__device__ __forceinline__ uint32_t packbf(float lo, float hi) {
    uint32_t r; asm("cvt.rn.bf16x2.f32 %0, %1, %2;" : "=r"(r) : "f"(hi), "f"(lo)); return r;
}
__device__ __forceinline__ float bflo(uint32_t u) { return __uint_as_float(u << 16); }
__device__ __forceinline__ float bfhi(uint32_t u) { return __uint_as_float(u & 0xFFFF0000u); }
__device__ __forceinline__ uint32_t sptr(const void* p) {
    return (uint32_t)__cvta_generic_to_shared(p);
}
__device__ __forceinline__ void cp16(uint32_t d, const void* s) {
    asm volatile("cp.async.cg.shared.global [%0], [%1], 16;" :: "r"(d), "l"(s));
}
#define CP_COMMIT() asm volatile("cp.async.commit_group;" ::: "memory")

#define MMA_BF16(acc, af, b0, b1) \
    asm volatile("mma.sync.aligned.m16n8k16.row.col.f32.bf16.bf16.f32 " \
        "{%0,%1,%2,%3}, {%4,%5,%6,%7}, {%8,%9}, {%0,%1,%2,%3};" \
        : "+f"((acc)[0]), "+f"((acc)[1]), "+f"((acc)[2]), "+f"((acc)[3]) \
        : "r"((af)[0]), "r"((af)[1]), "r"((af)[2]), "r"((af)[3]), \
          "r"(b0), "r"(b1))

// ================= fused prep =================
// idx space covers ctx packing; low indices also build weight slices.
__global__ void prep_all(const float* __restrict__ ctx,
                         const float* __restrict__ W1,
                         const float* __restrict__ W2)
{
    int idx = blockIdx.x * 256 + threadIdx.x;
    if (idx == 0) g_sum = 0.0;

    // ctx -> bf16 pairs
    if (idx < B_DIM * 256) {
        int row = idx >> 8, q = idx & 255;
        float v0 = ctx[(size_t)row * HD + 2 * q];
        float v1 = ctx[(size_t)row * HD + 2 * q + 1];
        g_ctxb[idx] = packbf(v0, v1);
    }
    // W1 ctx-part -> bf16 slices [c*16+kc][16q][128n]
    if (idx < 64 * 2048) {
        int si = idx >> 11, rem = idx & 2047;
        int q = rem >> 7, n = rem & 127;
        int c = si >> 4, kc = si & 15;
        int k0 = ZD + kc * 32 + 2 * q;
        float v0 = W1[(size_t)k0 * HD + c * 128 + n];
        float v1 = W1[(size_t)(k0 + 1) * HD + c * 128 + n];
        g_W1cb[idx] = packbf(v0, v1);
    }
    // loop weight slices (W1a + W2), same layout as before
    if (idx < 32 * 2048) {
        int si = idx >> 11, rem = idx & 2047;
        int q = rem >> 7, n = rem & 127;
        int c = si >> 3, ph = (si >> 2) & 1, kc = si & 3;
        float v0, v1;
        if (!ph) {
            int k0 = kc * 32 + 2 * q;
            v0 = W1[(size_t)k0 * HD + c * 128 + n];
            v1 = W1[(size_t)(k0 + 1) * HD + c * 128 + n];
        } else {
            int k0 = c * 128 + kc * 32 + 2 * q;
            v0 = W2[(size_t)k0 * ZD + n];
            v1 = W2[(size_t)(k0 + 1) * ZD + n];
        }
        g_Wsl[idx] = packbf(v0, v1);
    }
}

// ================= bf16 ctxproj =================
// tile 128x128, 8 warps (4m x 2n), warp tile 32x64, K=512 (16 chunks of 32k).
struct CS {
    uint32_t A[2][128][20];   // bf16x2 pairs, stride 20 -> conflict-free frag loads
    uint32_t Bm[2][16][136];
};

__global__ void __launch_bounds__(256, 2) ctxproj_bf16(const float* __restrict__ b1)
{
    __shared__ CS s;
    const int tid = threadIdx.x, lane = tid & 31, w = tid >> 5;
    const int wm = w >> 1, wn = w & 1;
    const int bcol = blockIdx.x, brow = blockIdx.y;
    const int grow0 = brow * 128;

    float acc[2][8][4] = {};

    // prefetch chunk 0
    #pragma unroll
    for (int i = 0; i < 2; i++) {
        int lin = tid + i * 256;
        int r = lin >> 2, q4 = (lin & 3) * 4;
        cp16(sptr(&s.A[0][r][q4]), g_ctxb + (size_t)(grow0 + r) * 256 + q4);
    }
    #pragma unroll
    for (int i = 0; i < 2; i++) {
        int lin = tid + i * 256;
        int kr = lin >> 5, n4 = (lin & 31) * 4;
        cp16(sptr(&s.Bm[0][kr][n4]), g_W1cb + (size_t)(bcol * 16) * 2048 + kr * 128 + n4);
    }
    CP_COMMIT();

    for (int kc = 0; kc < 16; kc++) {
        const int buf = kc & 1;
        if (kc + 1 < 16) {
            #pragma unroll
            for (int i = 0; i < 2; i++) {
                int lin = tid + i * 256;
                int r = lin >> 2, q4 = (lin & 3) * 4;
                cp16(sptr(&s.A[buf ^ 1][r][q4]),
                     g_ctxb + (size_t)(grow0 + r) * 256 + (kc + 1) * 16 + q4);
            }
            #pragma unroll
            for (int i = 0; i < 2; i++) {
                int lin = tid + i * 256;
                int kr = lin >> 5, n4 = (lin & 31) * 4;
                cp16(sptr(&s.Bm[buf ^ 1][kr][n4]),
                     g_W1cb + (size_t)(bcol * 16 + kc + 1) * 2048 + kr * 128 + n4);
            }
            CP_COMMIT();
            asm volatile("cp.async.wait_group 1;" ::: "memory");
        } else {
            asm volatile("cp.async.wait_group 0;" ::: "memory");
        }
        __syncthreads();

        #pragma unroll
        for (int kt = 0; kt < 2; kt++) {
            const int qa = kt * 8 + (lane & 3);
            uint32_t af[2][4];
            #pragma unroll
            for (int mt = 0; mt < 2; mt++) {
                int r = wm * 32 + mt * 16 + (lane >> 2);
                af[mt][0] = s.A[buf][r][qa];
                af[mt][1] = s.A[buf][r + 8][qa];
                af[mt][2] = s.A[buf][r][qa + 4];
                af[mt][3] = s.A[buf][r + 8][qa + 4];
            }
            #pragma unroll
            for (int nt = 0; nt < 8; nt++) {
                int nn = wn * 64 + nt * 8 + (lane >> 2);
                uint32_t b0 = s.Bm[buf][qa][nn];
                uint32_t b1 = s.Bm[buf][qa + 4][nn];
                #pragma unroll
                for (int mt = 0; mt < 2; mt++)
                    MMA_BF16(acc[mt][nt], af[mt], b0, b1);
            }
        }
        __syncthreads();
    }

    // epilogue: + b1, pack bf16, store
    #pragma unroll
    for (int mt = 0; mt < 2; mt++) {
        #pragma unroll
        for (int nt = 0; nt < 8; nt++) {
            int r = grow0 + wm * 32 + mt * 16 + (lane >> 2);
            int c = bcol * 128 + wn * 64 + nt * 8 + 2 * (lane & 3);
            float2 bv = *reinterpret_cast<const float2*>(&b1[c]);
            g_ctxpb[(size_t)r * 256 + (c >> 1)] =
                packbf(acc[mt][nt][0] + bv.x, acc[mt][nt][1] + bv.y);
            g_ctxpb[(size_t)(r + 8) * 256 + (c >> 1)] =
                packbf(acc[mt][nt][2] + bv.x, acc[mt][nt][3] + bv.y);
        }
    }
}

// ================= persistent bf16 step kernel (UNCHANGED from 766us best) =================
// 64-row CTAs, 2 CTAs/SM. 4 warps (2m x 2n), warp tile 32x64.
struct PS {
    float    zf[64][130];
    uint32_t zb[64][68];
    uint32_t hb[64][68];
    uint32_t wb[4][16][136];
};
#define PS_SZ ((int)sizeof(PS))

extern __shared__ char dynsm[];

__device__ __forceinline__ void mma_slice(
    float acc[2][8][4], const uint32_t (&A)[64][68], int qb,
    const uint32_t (&Bm)[16][136], int lane, int wm, int wn)
{
    #pragma unroll
    for (int kt = 0; kt < 2; kt++) {
        const int qa = qb + kt * 8 + (lane & 3);
        uint32_t af[2][4];
        #pragma unroll
        for (int mt = 0; mt < 2; mt++) {
            int r = wm * 32 + mt * 16 + (lane >> 2);
            af[mt][0] = A[r][qa];
            af[mt][1] = A[r + 8][qa];
            af[mt][2] = A[r][qa + 4];
            af[mt][3] = A[r + 8][qa + 4];
        }
        const int kq = kt * 8 + (lane & 3);
        #pragma unroll
        for (int nt = 0; nt < 8; nt++) {
            int nn = wn * 64 + nt * 8 + (lane >> 2);
            uint32_t b0 = Bm[kq][nn];
            uint32_t b1 = Bm[kq + 4][nn];
            #pragma unroll
            for (int mt = 0; mt < 2; mt++)
                MMA_BF16(acc[mt][nt], af[mt], b0, b1);
        }
    }
}

__global__ void __launch_bounds__(128, 2) step_kernel(
    const float* __restrict__ eps0, const float* __restrict__ eps,
    const float* __restrict__ beta, const float* __restrict__ sigma0,
    const float* __restrict__ b2,   const float* __restrict__ temb,
    const float* __restrict__ tmu)
{
    PS* s = (PS*)dynsm;
    const int tid = threadIdx.x, lane = tid & 31, w = tid >> 5;
    const int wm = w >> 1, wn = w & 1;
    const int grow0 = blockIdx.x * 64;

    const float s0 = sigma0[0];
    const float lg = logf(s0);
    const float dt = 1.0f / TSTEPS;
    double ssum = 0.0;

    {
        float local = 0.f;
        #pragma unroll
        for (int i = 0; i < 16; i++) {
            int lin = (tid + i * 128) * 4;
            int row = lin >> 7, col = lin & 127;
            float4 e = *reinterpret_cast<const float4*>(&eps0[(size_t)(grow0 + row) * ZD + col]);
            float z0 = s0 * e.x, z1 = s0 * e.y, z2 = s0 * e.z, z3 = s0 * e.w;
            s->zf[row][col + 0] = z0; s->zf[row][col + 1] = z1;
            s->zf[row][col + 2] = z2; s->zf[row][col + 3] = z3;
            s->zb[row][(col >> 1) + 0] = packbf(z0, z1);
            s->zb[row][(col >> 1) + 1] = packbf(z2, z3);
            local += 0.5f * (e.x * e.x + e.y * e.y + e.z * e.z + e.w * e.w) + 4.f * lg;
        }
        ssum += (double)local;
    }

#define ISSUE_GROUP(gv) do { \
    const uint32_t* _src = g_Wsl + (((gv) & 15) * 2) * 2048; \
    const int _slot0 = ((gv) & 1) * 2; \
    _Pragma("unroll") \
    for (int _i = 0; _i < 8; _i++) { \
        int _j = tid + _i * 128; \
        int _sl = _j >> 9, _rem = _j & 511; \
        cp16(sptr(&s->wb[_slot0 + _sl][_rem >> 5][(_rem & 31) * 4]), \
             _src + _sl * 2048 + _rem * 4); \
    } \
    CP_COMMIT(); \
} while (0)

#define GROUP_SYNC() do { \
    asm volatile("cp.async.wait_group 0;" ::: "memory"); \
    __syncthreads(); \
} while (0)

    ISSUE_GROUP(0);

    int g = 0;
    for (int t = 0; t < TSTEPS; t++) {
        const float beta_f = __ldg(&beta[t]);
        const float beta_b = __ldg(&beta[(t + TSTEPS - 1) % TSTEPS]);
        const float sig_f = sqrtf(2.0f * beta_f * dt) * s0;
        const float sig_b = sqrtf(2.0f * beta_b * dt) * s0;
        const float inv_sb = 1.0f / sig_b;
        const float logdiff = logf(sig_f) - logf(sig_b);
        const float* eps_t = eps + ((size_t)t * B_DIM + grow0) * ZD;

        float accu[2][8][4] = {};

        for (int c = 0; c < 4; c++) {
            float acch[2][8][4] = {};
            #pragma unroll
            for (int half = 0; half < 2; half++) {
                GROUP_SYNC();
                ISSUE_GROUP(g + 1);
                const int slot0 = (g & 1) * 2;
                mma_slice(acch, s->zb, (half * 2 + 0) * 16, s->wb[slot0 + 0], lane, wm, wn);
                mma_slice(acch, s->zb, (half * 2 + 1) * 16, s->wb[slot0 + 1], lane, wm, wn);
                g++;
            }
            #pragma unroll
            for (int nt = 0; nt < 8; nt++) {
                int gc = c * 128 + wn * 64 + nt * 8 + 2 * (lane & 3);
                float2 te = *reinterpret_cast<const float2*>(&temb[(size_t)t * HD + gc]);
                int lq = wn * 32 + nt * 4 + (lane & 3);
                #pragma unroll
                for (int mt = 0; mt < 2; mt++) {
                    int r = wm * 32 + mt * 16 + (lane >> 2);
                    #pragma unroll
                    for (int hf = 0; hf < 2; hf++) {
                        int rr = r + 8 * hf;
                        uint32_t cpv = __ldg(&g_ctxpb[(size_t)(grow0 + rr) * 256 + c * 64 + lq]);
                        float v0 = acch[mt][nt][hf * 2 + 0] + bflo(cpv) + te.x;
                        float v1 = acch[mt][nt][hf * 2 + 1] + bfhi(cpv) + te.y;
                        s->hb[rr][lq] = packbf(fmaxf(v0, 0.f), fmaxf(v1, 0.f));
                    }
                }
            }
            #pragma unroll
            for (int half = 0; half < 2; half++) {
                GROUP_SYNC();
                ISSUE_GROUP(g + 1);
                const int slot0 = (g & 1) * 2;
                mma_slice(accu, s->hb, (half * 2 + 0) * 16, s->wb[slot0 + 0], lane, wm, wn);
                mma_slice(accu, s->hb, (half * 2 + 1) * 16, s->wb[slot0 + 1], lane, wm, wn);
                g++;
            }
        }

        float local = 0.f;
        #pragma unroll
        for (int nt = 0; nt < 8; nt++) {
            int cc = wn * 64 + nt * 8 + 2 * (lane & 3);
            float2 bv = *reinterpret_cast<const float2*>(&b2[cc]);
            #pragma unroll
            for (int mt = 0; mt < 2; mt++) {
                int r = wm * 32 + mt * 16 + (lane >> 2);
                #pragma unroll
                for (int hf = 0; hf < 2; hf++) {
                    int rr = r + 8 * hf;
                    float2 zp = *reinterpret_cast<const float2*>(&s->zf[rr][cc]);
                    float2 ev = *reinterpret_cast<const float2*>(&eps_t[(size_t)rr * ZD + cc]);
                    float u0 = accu[mt][nt][hf * 2 + 0] + bv.x;
                    float u1 = accu[mt][nt][hf * 2 + 1] + bv.y;
                    float mu0 = zp.x + (beta_f * zp.x + u0) * dt;
                    float mu1 = zp.y + (beta_f * zp.y + u1) * dt;
                    float zn0 = fmaf(sig_f, ev.x, mu0);
                    float zn1 = fmaf(sig_f, ev.y, mu1);
                    float mb0 = zn0 - beta_b * zn0 * dt;
                    float mb1 = zn1 - beta_b * zn1 * dt;
                    float a10 = (zp.x - mb0) * inv_sb;
                    float a11 = (zp.y - mb1) * inv_sb;
                    local += 0.5f * (ev.x * ev.x - a10 * a10) + logdiff;
                    local += 0.5f * (ev.y * ev.y - a11 * a11) + logdiff;
                    if (t == TSTEPS - 1) {
                        float2 tm = *reinterpret_cast<const float2*>(
                            &tmu[(size_t)(grow0 + rr) * ZD + cc]);
                        float d0 = zn0 - tm.x, d1 = zn1 - tm.y;
                        local -= 0.5f * (d0 * d0 + d1 * d1);
                    }
                    float2 zo = { zn0, zn1 };
                    *reinterpret_cast<float2*>(&s->zf[rr][cc]) = zo;
                    s->zb[rr][cc >> 1] = packbf(zn0, zn1);
                }
            }
        }
        ssum += (double)local;
    }

    asm volatile("cp.async.wait_group 0;" ::: "memory");
    __syncthreads();
    double* red = reinterpret_cast<double*>(&s->wb[0][0][0]);
    red[tid] = ssum;
    __syncthreads();
    for (int st = 64; st > 0; st >>= 1) {
        if (tid < st) red[tid] += red[tid + st];
        __syncthreads();
    }
    if (tid == 0) atomicAdd(&g_sum, red[0]);
}

__global__ void write_out(float* __restrict__ out)
{
    out[0] = (float)(g_sum / (double)B_DIM);
}

// ---------------- host launcher ----------------
extern "C" void kernel_launch(void* const* d_in, const int* in_sizes, int n_in,
                              void* d_out, int out_size)
{
    (void)in_sizes; (void)n_in; (void)out_size;
    const float* ctx    = (const float*)d_in[0];
    const float* eps0   = (const float*)d_in[1];
    const float* eps    = (const float*)d_in[2];
    const float* beta   = (const float*)d_in[3];
    const float* sigma0 = (const float*)d_in[4];
    const float* W1     = (const float*)d_in[5];
    const float* b1     = (const float*)d_in[6];
    const float* W2     = (const float*)d_in[7];
    const float* b2     = (const float*)d_in[8];
    const float* temb   = (const float*)d_in[9];
    const float* tmu    = (const float*)d_in[10];
    float* out = (float*)d_out;

    cudaFuncSetAttribute(step_kernel, cudaFuncAttributeMaxDynamicSharedMemorySize, PS_SZ);

    prep_all<<<B_DIM, 256>>>(ctx, W1, W2);
    ctxproj_bf16<<<dim3(4, 128), 256>>>(b1);
    step_kernel<<<256, 128, PS_SZ>>>(eps0, eps, beta, sigma0, b2, temb, tmu);
    write_out<<<1, 1>>>(out);
}

// round 14
// speedup vs baseline: 1.1231x; 1.0024x over previous
#include <cuda_runtime.h>
#include <cstdint>
#include <math.h>

#define B_DIM  16384
#define ZD     128
#define HD     512
#define TSTEPS 32

// ---------------- device global scratch ----------------
__device__ __align__(16) uint32_t g_ctxb[(size_t)B_DIM * 256]; // ctx packed bf16x2 pairs
__device__ __align__(16) uint32_t g_W1cb[64 * 2048];           // W1[128:640,:] bf16 slices [16q][128n]
__device__ __align__(16) uint32_t g_ctxpb[(size_t)B_DIM * 256]; // ctxproj, packed bf16x2 pairs
__device__ __align__(16) uint32_t g_Wsl[32 * 2048];             // 32 loop weight slices [16q][128n]
__device__ double g_sum;
__device__ int    g_done;

// ---------------- helpers ----------------
__device__ __forceinline__ uint32_t packbf(float lo, float hi) {
    uint32_t r; asm("cvt.rn.bf16x2.f32 %0, %1, %2;" : "=r"(r) : "f"(hi), "f"(lo)); return r;
}
__device__ __forceinline__ float bflo(uint32_t u) { return __uint_as_float(u << 16); }
__device__ __forceinline__ float bfhi(uint32_t u) { return __uint_as_float(u & 0xFFFF0000u); }
__device__ __forceinline__ uint32_t sptr(const void* p) {
    return (uint32_t)__cvta_generic_to_shared(p);
}
__device__ __forceinline__ void cp16(uint32_t d, const void* s) {
    asm volatile("cp.async.cg.shared.global [%0], [%1], 16;" :: "r"(d), "l"(s));
}
#define CP_COMMIT() asm volatile("cp.async.commit_group;" ::: "memory")

#define MMA_BF16(acc, af, b0, b1) \
    asm volatile("mma.sync.aligned.m16n8k16.row.col.f32.bf16.bf16.f32 " \
        "{%0,%1,%2,%3}, {%4,%5,%6,%7}, {%8,%9}, {%0,%1,%2,%3};" \
        : "+f"((acc)[0]), "+f"((acc)[1]), "+f"((acc)[2]), "+f"((acc)[3]) \
        : "r"((af)[0]), "r"((af)[1]), "r"((af)[2]), "r"((af)[3]), \
          "r"(b0), "r"(b1))

// ================= fused prep =================
__global__ void prep_all(const float* __restrict__ ctx,
                         const float* __restrict__ W1,
                         const float* __restrict__ W2)
{
    int idx = blockIdx.x * 256 + threadIdx.x;
    if (idx == 0) g_sum = 0.0;

    if (idx < B_DIM * 256) {
        int row = idx >> 8, q = idx & 255;
        float v0 = ctx[(size_t)row * HD + 2 * q];
        float v1 = ctx[(size_t)row * HD + 2 * q + 1];
        g_ctxb[idx] = packbf(v0, v1);
    }
    if (idx < 64 * 2048) {
        int si = idx >> 11, rem = idx & 2047;
        int q = rem >> 7, n = rem & 127;
        int c = si >> 4, kc = si & 15;
        int k0 = ZD + kc * 32 + 2 * q;
        float v0 = W1[(size_t)k0 * HD + c * 128 + n];
        float v1 = W1[(size_t)(k0 + 1) * HD + c * 128 + n];
        g_W1cb[idx] = packbf(v0, v1);
    }
    if (idx < 32 * 2048) {
        int si = idx >> 11, rem = idx & 2047;
        int q = rem >> 7, n = rem & 127;
        int c = si >> 3, ph = (si >> 2) & 1, kc = si & 3;
        float v0, v1;
        if (!ph) {
            int k0 = kc * 32 + 2 * q;
            v0 = W1[(size_t)k0 * HD + c * 128 + n];
            v1 = W1[(size_t)(k0 + 1) * HD + c * 128 + n];
        } else {
            int k0 = c * 128 + kc * 32 + 2 * q;
            v0 = W2[(size_t)k0 * ZD + n];
            v1 = W2[(size_t)(k0 + 1) * ZD + n];
        }
        g_Wsl[idx] = packbf(v0, v1);
    }
}

// ================= bf16 ctxproj (unchanged from 724us best) =================
struct CS {
    uint32_t A[2][128][20];
    uint32_t Bm[2][16][136];
};

__global__ void __launch_bounds__(256, 2) ctxproj_bf16(const float* __restrict__ b1)
{
    __shared__ CS s;
    const int tid = threadIdx.x, lane = tid & 31, w = tid >> 5;
    const int wm = w >> 1, wn = w & 1;
    const int bcol = blockIdx.x, brow = blockIdx.y;
    const int grow0 = brow * 128;

    float acc[2][8][4] = {};

    #pragma unroll
    for (int i = 0; i < 2; i++) {
        int lin = tid + i * 256;
        int r = lin >> 2, q4 = (lin & 3) * 4;
        cp16(sptr(&s.A[0][r][q4]), g_ctxb + (size_t)(grow0 + r) * 256 + q4);
    }
    #pragma unroll
    for (int i = 0; i < 2; i++) {
        int lin = tid + i * 256;
        int kr = lin >> 5, n4 = (lin & 31) * 4;
        cp16(sptr(&s.Bm[0][kr][n4]), g_W1cb + (size_t)(bcol * 16) * 2048 + kr * 128 + n4);
    }
    CP_COMMIT();

    for (int kc = 0; kc < 16; kc++) {
        const int buf = kc & 1;
        if (kc + 1 < 16) {
            #pragma unroll
            for (int i = 0; i < 2; i++) {
                int lin = tid + i * 256;
                int r = lin >> 2, q4 = (lin & 3) * 4;
                cp16(sptr(&s.A[buf ^ 1][r][q4]),
                     g_ctxb + (size_t)(grow0 + r) * 256 + (kc + 1) * 16 + q4);
            }
            #pragma unroll
            for (int i = 0; i < 2; i++) {
                int lin = tid + i * 256;
                int kr = lin >> 5, n4 = (lin & 31) * 4;
                cp16(sptr(&s.Bm[buf ^ 1][kr][n4]),
                     g_W1cb + (size_t)(bcol * 16 + kc + 1) * 2048 + kr * 128 + n4);
            }
            CP_COMMIT();
            asm volatile("cp.async.wait_group 1;" ::: "memory");
        } else {
            asm volatile("cp.async.wait_group 0;" ::: "memory");
        }
        __syncthreads();

        #pragma unroll
        for (int kt = 0; kt < 2; kt++) {
            const int qa = kt * 8 + (lane & 3);
            uint32_t af[2][4];
            #pragma unroll
            for (int mt = 0; mt < 2; mt++) {
                int r = wm * 32 + mt * 16 + (lane >> 2);
                af[mt][0] = s.A[buf][r][qa];
                af[mt][1] = s.A[buf][r + 8][qa];
                af[mt][2] = s.A[buf][r][qa + 4];
                af[mt][3] = s.A[buf][r + 8][qa + 4];
            }
            #pragma unroll
            for (int nt = 0; nt < 8; nt++) {
                int nn = wn * 64 + nt * 8 + (lane >> 2);
                uint32_t b0 = s.Bm[buf][qa][nn];
                uint32_t b1 = s.Bm[buf][qa + 4][nn];
                #pragma unroll
                for (int mt = 0; mt < 2; mt++)
                    MMA_BF16(acc[mt][nt], af[mt], b0, b1);
            }
        }
        __syncthreads();
    }

    #pragma unroll
    for (int mt = 0; mt < 2; mt++) {
        #pragma unroll
        for (int nt = 0; nt < 8; nt++) {
            int r = grow0 + wm * 32 + mt * 16 + (lane >> 2);
            int c = bcol * 128 + wn * 64 + nt * 8 + 2 * (lane & 3);
            float2 bv = *reinterpret_cast<const float2*>(&b1[c]);
            g_ctxpb[(size_t)r * 256 + (c >> 1)] =
                packbf(acc[mt][nt][0] + bv.x, acc[mt][nt][1] + bv.y);
            g_ctxpb[(size_t)(r + 8) * 256 + (c >> 1)] =
                packbf(acc[mt][nt][2] + bv.x, acc[mt][nt][3] + bv.y);
        }
    }
}

// ================= persistent bf16 step kernel =================
// 64-row CTAs, 2 CTAs/SM. 4 warps (2m x 2n), warp tile 32x64.
// z A-fragments cached in registers once per step (64 regs).
struct PS {
    float    zf[64][130];
    uint32_t zb[64][68];
    uint32_t hb[64][68];
    uint32_t wb[4][16][136];
};
#define PS_SZ ((int)sizeof(PS))

extern __shared__ char dynsm[];

// MMA with A fragments already in registers (z path)
__device__ __forceinline__ void mma_slice_zreg(
    float acc[2][8][4], const uint32_t (&af)[2][2][4],
    const uint32_t (&Bm)[16][136], int lane, int wn)
{
    #pragma unroll
    for (int kt = 0; kt < 2; kt++) {
        const int kq = kt * 8 + (lane & 3);
        #pragma unroll
        for (int nt = 0; nt < 8; nt++) {
            int nn = wn * 64 + nt * 8 + (lane >> 2);
            uint32_t b0 = Bm[kq][nn];
            uint32_t b1 = Bm[kq + 4][nn];
            #pragma unroll
            for (int mt = 0; mt < 2; mt++)
                MMA_BF16(acc[mt][nt], af[kt][mt], b0, b1);
        }
    }
}

// MMA loading A fragments from smem (h path)
__device__ __forceinline__ void mma_slice(
    float acc[2][8][4], const uint32_t (&A)[64][68], int qb,
    const uint32_t (&Bm)[16][136], int lane, int wm, int wn)
{
    #pragma unroll
    for (int kt = 0; kt < 2; kt++) {
        const int qa = qb + kt * 8 + (lane & 3);
        uint32_t af[2][4];
        #pragma unroll
        for (int mt = 0; mt < 2; mt++) {
            int r = wm * 32 + mt * 16 + (lane >> 2);
            af[mt][0] = A[r][qa];
            af[mt][1] = A[r + 8][qa];
            af[mt][2] = A[r][qa + 4];
            af[mt][3] = A[r + 8][qa + 4];
        }
        const int kq = kt * 8 + (lane & 3);
        #pragma unroll
        for (int nt = 0; nt < 8; nt++) {
            int nn = wn * 64 + nt * 8 + (lane >> 2);
            uint32_t b0 = Bm[kq][nn];
            uint32_t b1 = Bm[kq + 4][nn];
            #pragma unroll
            for (int mt = 0; mt < 2; mt++)
                MMA_BF16(acc[mt][nt], af[mt], b0, b1);
        }
    }
}

__global__ void __launch_bounds__(128, 2) step_kernel(
    const float* __restrict__ eps0, const float* __restrict__ eps,
    const float* __restrict__ beta, const float* __restrict__ sigma0,
    const float* __restrict__ b2,   const float* __restrict__ temb,
    const float* __restrict__ tmu,  float* __restrict__ out)
{
    PS* s = (PS*)dynsm;
    const int tid = threadIdx.x, lane = tid & 31, w = tid >> 5;
    const int wm = w >> 1, wn = w & 1;
    const int grow0 = blockIdx.x * 64;

    const float s0 = sigma0[0];
    const float lg = logf(s0);
    const float dt = 1.0f / TSTEPS;
    double ssum = 0.0;

    {
        float local = 0.f;
        #pragma unroll
        for (int i = 0; i < 16; i++) {
            int lin = (tid + i * 128) * 4;
            int row = lin >> 7, col = lin & 127;
            float4 e = *reinterpret_cast<const float4*>(&eps0[(size_t)(grow0 + row) * ZD + col]);
            float z0 = s0 * e.x, z1 = s0 * e.y, z2 = s0 * e.z, z3 = s0 * e.w;
            s->zf[row][col + 0] = z0; s->zf[row][col + 1] = z1;
            s->zf[row][col + 2] = z2; s->zf[row][col + 3] = z3;
            s->zb[row][(col >> 1) + 0] = packbf(z0, z1);
            s->zb[row][(col >> 1) + 1] = packbf(z2, z3);
            local += 0.5f * (e.x * e.x + e.y * e.y + e.z * e.z + e.w * e.w) + 4.f * lg;
        }
        ssum += (double)local;
    }

#define ISSUE_GROUP(gv) do { \
    const uint32_t* _src = g_Wsl + (((gv) & 15) * 2) * 2048; \
    const int _slot0 = ((gv) & 1) * 2; \
    _Pragma("unroll") \
    for (int _i = 0; _i < 8; _i++) { \
        int _j = tid + _i * 128; \
        int _sl = _j >> 9, _rem = _j & 511; \
        cp16(sptr(&s->wb[_slot0 + _sl][_rem >> 5][(_rem & 31) * 4]), \
             _src + _sl * 2048 + _rem * 4); \
    } \
    CP_COMMIT(); \
} while (0)

#define GROUP_SYNC() do { \
    asm volatile("cp.async.wait_group 0;" ::: "memory"); \
    __syncthreads(); \
} while (0)

    ISSUE_GROUP(0);

    int g = 0;
    for (int t = 0; t < TSTEPS; t++) {
        const float beta_f = __ldg(&beta[t]);
        const float beta_b = __ldg(&beta[(t + TSTEPS - 1) % TSTEPS]);
        const float sig_f = sqrtf(2.0f * beta_f * dt) * s0;
        const float sig_b = sqrtf(2.0f * beta_b * dt) * s0;
        const float inv_sb = 1.0f / sig_b;
        const float logdiff = logf(sig_f) - logf(sig_b);
        const float* eps_t = eps + ((size_t)t * B_DIM + grow0) * ZD;

        float accu[2][8][4] = {};
        uint32_t za[4][2][2][4];   // z A-fragments, loaded once per step

        #pragma unroll 1
        for (int c = 0; c < 4; c++) {
            float acch[2][8][4] = {};
            // ---- MMA1: acch = z @ W1a[:, c]  (2 groups of 2 slices) ----
            #pragma unroll
            for (int half = 0; half < 2; half++) {
                GROUP_SYNC();
                if (c == 0 && half == 0) {
                    // load z fragments for the whole step (zb stable after this sync)
                    #pragma unroll
                    for (int kc = 0; kc < 4; kc++)
                        #pragma unroll
                        for (int kt = 0; kt < 2; kt++) {
                            int qa = kc * 16 + kt * 8 + (lane & 3);
                            #pragma unroll
                            for (int mt = 0; mt < 2; mt++) {
                                int r = wm * 32 + mt * 16 + (lane >> 2);
                                za[kc][kt][mt][0] = s->zb[r][qa];
                                za[kc][kt][mt][1] = s->zb[r + 8][qa];
                                za[kc][kt][mt][2] = s->zb[r][qa + 4];
                                za[kc][kt][mt][3] = s->zb[r + 8][qa + 4];
                            }
                        }
                }
                ISSUE_GROUP(g + 1);
                const int slot0 = (g & 1) * 2;
                mma_slice_zreg(acch, za[half * 2 + 0], s->wb[slot0 + 0], lane, wn);
                mma_slice_zreg(acch, za[half * 2 + 1], s->wb[slot0 + 1], lane, wn);
                g++;
            }
            // ---- epilogue1: h = bf16(relu(acch + ctxp + te)) -> hb ----
            #pragma unroll
            for (int nt = 0; nt < 8; nt++) {
                int gc = c * 128 + wn * 64 + nt * 8 + 2 * (lane & 3);
                float2 te = *reinterpret_cast<const float2*>(&temb[(size_t)t * HD + gc]);
                int lq = wn * 32 + nt * 4 + (lane & 3);
                #pragma unroll
                for (int mt = 0; mt < 2; mt++) {
                    int r = wm * 32 + mt * 16 + (lane >> 2);
                    #pragma unroll
                    for (int hf = 0; hf < 2; hf++) {
                        int rr = r + 8 * hf;
                        uint32_t cpv = __ldg(&g_ctxpb[(size_t)(grow0 + rr) * 256 + c * 64 + lq]);
                        float v0 = acch[mt][nt][hf * 2 + 0] + bflo(cpv) + te.x;
                        float v1 = acch[mt][nt][hf * 2 + 1] + bfhi(cpv) + te.y;
                        s->hb[rr][lq] = packbf(fmaxf(v0, 0.f), fmaxf(v1, 0.f));
                    }
                }
            }
            // ---- MMA2: accu += h @ W2[c, :]  (2 groups of 2 slices) ----
            #pragma unroll
            for (int half = 0; half < 2; half++) {
                GROUP_SYNC();
                ISSUE_GROUP(g + 1);
                const int slot0 = (g & 1) * 2;
                mma_slice(accu, s->hb, (half * 2 + 0) * 16, s->wb[slot0 + 0], lane, wm, wn);
                mma_slice(accu, s->hb, (half * 2 + 1) * 16, s->wb[slot0 + 1], lane, wm, wn);
                g++;
            }
        }

        // ---- update epilogue ----
        float local = 0.f;
        #pragma unroll
        for (int nt = 0; nt < 8; nt++) {
            int cc = wn * 64 + nt * 8 + 2 * (lane & 3);
            float2 bv = *reinterpret_cast<const float2*>(&b2[cc]);
            #pragma unroll
            for (int mt = 0; mt < 2; mt++) {
                int r = wm * 32 + mt * 16 + (lane >> 2);
                #pragma unroll
                for (int hf = 0; hf < 2; hf++) {
                    int rr = r + 8 * hf;
                    float2 zp = *reinterpret_cast<const float2*>(&s->zf[rr][cc]);
                    float2 ev = *reinterpret_cast<const float2*>(&eps_t[(size_t)rr * ZD + cc]);
                    float u0 = accu[mt][nt][hf * 2 + 0] + bv.x;
                    float u1 = accu[mt][nt][hf * 2 + 1] + bv.y;
                    float mu0 = zp.x + (beta_f * zp.x + u0) * dt;
                    float mu1 = zp.y + (beta_f * zp.y + u1) * dt;
                    float zn0 = fmaf(sig_f, ev.x, mu0);
                    float zn1 = fmaf(sig_f, ev.y, mu1);
                    float mb0 = zn0 - beta_b * zn0 * dt;
                    float mb1 = zn1 - beta_b * zn1 * dt;
                    float a10 = (zp.x - mb0) * inv_sb;
                    float a11 = (zp.y - mb1) * inv_sb;
                    local += 0.5f * (ev.x * ev.x - a10 * a10) + logdiff;
                    local += 0.5f * (ev.y * ev.y - a11 * a11) + logdiff;
                    if (t == TSTEPS - 1) {
                        float2 tm = *reinterpret_cast<const float2*>(
                            &tmu[(size_t)(grow0 + rr) * ZD + cc]);
                        float d0 = zn0 - tm.x, d1 = zn1 - tm.y;
                        local -= 0.5f * (d0 * d0 + d1 * d1);
                    }
                    float2 zo = { zn0, zn1 };
                    *reinterpret_cast<float2*>(&s->zf[rr][cc]) = zo;
                    s->zb[rr][cc >> 1] = packbf(zn0, zn1);
                }
            }
        }
        ssum += (double)local;
    }

    // ---- reduce + fused output ----
    asm volatile("cp.async.wait_group 0;" ::: "memory");
    __syncthreads();
    double* red = reinterpret_cast<double*>(&s->wb[0][0][0]);
    red[tid] = ssum;
    __syncthreads();
    for (int st = 64; st > 0; st >>= 1) {
        if (tid < st) red[tid] += red[tid + st];
        __syncthreads();
    }
    if (tid == 0) {
        atomicAdd(&g_sum, red[0]);
        __threadfence();
        int done = atomicAdd(&g_done, 1);
        if (done == (int)gridDim.x - 1) {
            double total = atomicAdd(&g_sum, 0.0);
            out[0] = (float)(total / (double)B_DIM);
            g_done = 0;
        }
    }
}

// ---------------- host launcher ----------------
extern "C" void kernel_launch(void* const* d_in, const int* in_sizes, int n_in,
                              void* d_out, int out_size)
{
    (void)in_sizes; (void)n_in; (void)out_size;
    const float* ctx    = (const float*)d_in[0];
    const float* eps0   = (const float*)d_in[1];
    const float* eps    = (const float*)d_in[2];
    const float* beta   = (const float*)d_in[3];
    const float* sigma0 = (const float*)d_in[4];
    const float* W1     = (const float*)d_in[5];
    const float* b1     = (const float*)d_in[6];
    const float* W2     = (const float*)d_in[7];
    const float* b2     = (const float*)d_in[8];
    const float* temb   = (const float*)d_in[9];
    const float* tmu    = (const float*)d_in[10];
    float* out = (float*)d_out;

    cudaFuncSetAttribute(step_kernel, cudaFuncAttributeMaxDynamicSharedMemorySize, PS_SZ);

    prep_all<<<B_DIM, 256>>>(ctx, W1, W2);
    ctxproj_bf16<<<dim3(4, 128), 256>>>(b1);
    step_kernel<<<256, 128, PS_SZ>>>(eps0, eps, beta, sigma0, b2, temb, tmu, out);
}

// round 15
// speedup vs baseline: 1.2903x; 1.1488x over previous
#include <cuda_runtime.h>
#include <cstdint>
#include <math.h>

#define B_DIM  16384
#define ZD     128
#define HD     512
#define TSTEPS 32

// ---------------- device global scratch ----------------
__device__ __align__(16) uint32_t g_ctxb[(size_t)B_DIM * 256]; // ctx packed bf16x2 pairs
__device__ __align__(16) uint32_t g_W1cb[64 * 2048];           // W1[128:640,:] bf16 slices [16q][128n]
__device__ __align__(16) uint4    g_ctxpf[256 * 4 * 8 * 128];  // ctxproj, step-fragment layout
__device__ __align__(16) uint32_t g_Wsl[32 * 2048];            // 32 loop weight slices [16q][128n]
__device__ double g_sum;
__device__ int    g_done;

// ---------------- helpers ----------------
__device__ __forceinline__ uint32_t packbf(float lo, float hi) {
    uint32_t r; asm("cvt.rn.bf16x2.f32 %0, %1, %2;" : "=r"(r) : "f"(hi), "f"(lo)); return r;
}
__device__ __forceinline__ float bflo(uint32_t u) { return __uint_as_float(u << 16); }
__device__ __forceinline__ float bfhi(uint32_t u) { return __uint_as_float(u & 0xFFFF0000u); }
__device__ __forceinline__ uint32_t sptr(const void* p) {
    return (uint32_t)__cvta_generic_to_shared(p);
}
__device__ __forceinline__ void cp16(uint32_t d, const void* s) {
    asm volatile("cp.async.cg.shared.global [%0], [%1], 16;" :: "r"(d), "l"(s));
}
#define CP_COMMIT() asm volatile("cp.async.commit_group;" ::: "memory")

#define MMA_BF16(acc, af, b0, b1) \
    asm volatile("mma.sync.aligned.m16n8k16.row.col.f32.bf16.bf16.f32 " \
        "{%0,%1,%2,%3}, {%4,%5,%6,%7}, {%8,%9}, {%0,%1,%2,%3};" \
        : "+f"((acc)[0]), "+f"((acc)[1]), "+f"((acc)[2]), "+f"((acc)[3]) \
        : "r"((af)[0]), "r"((af)[1]), "r"((af)[2]), "r"((af)[3]), \
          "r"(b0), "r"(b1))

// ================= fused prep =================
__global__ void prep_all(const float* __restrict__ ctx,
                         const float* __restrict__ W1,
                         const float* __restrict__ W2)
{
    int idx = blockIdx.x * 256 + threadIdx.x;
    if (idx == 0) g_sum = 0.0;

    if (idx < B_DIM * 256) {
        int row = idx >> 8, q = idx & 255;
        float v0 = ctx[(size_t)row * HD + 2 * q];
        float v1 = ctx[(size_t)row * HD + 2 * q + 1];
        g_ctxb[idx] = packbf(v0, v1);
    }
    if (idx < 64 * 2048) {
        int si = idx >> 11, rem = idx & 2047;
        int q = rem >> 7, n = rem & 127;
        int c = si >> 4, kc = si & 15;
        int k0 = ZD + kc * 32 + 2 * q;
        float v0 = W1[(size_t)k0 * HD + c * 128 + n];
        float v1 = W1[(size_t)(k0 + 1) * HD + c * 128 + n];
        g_W1cb[idx] = packbf(v0, v1);
    }
    if (idx < 32 * 2048) {
        int si = idx >> 11, rem = idx & 2047;
        int q = rem >> 7, n = rem & 127;
        int c = si >> 3, ph = (si >> 2) & 1, kc = si & 3;
        float v0, v1;
        if (!ph) {
            int k0 = kc * 32 + 2 * q;
            v0 = W1[(size_t)k0 * HD + c * 128 + n];
            v1 = W1[(size_t)(k0 + 1) * HD + c * 128 + n];
        } else {
            int k0 = c * 128 + kc * 32 + 2 * q;
            v0 = W2[(size_t)k0 * ZD + n];
            v1 = W2[(size_t)(k0 + 1) * ZD + n];
        }
        g_Wsl[idx] = packbf(v0, v1);
    }
}

// ================= bf16 ctxproj =================
struct CS {
    uint32_t A[2][128][20];
    uint32_t Bm[2][16][136];
};

__global__ void __launch_bounds__(256, 2) ctxproj_bf16(const float* __restrict__ b1)
{
    __shared__ CS s;
    const int tid = threadIdx.x, lane = tid & 31, w = tid >> 5;
    const int wm = w >> 1, wn = w & 1;
    const int bcol = blockIdx.x, brow = blockIdx.y;
    const int grow0 = brow * 128;

    float acc[2][8][4] = {};

    #pragma unroll
    for (int i = 0; i < 2; i++) {
        int lin = tid + i * 256;
        int r = lin >> 2, q4 = (lin & 3) * 4;
        cp16(sptr(&s.A[0][r][q4]), g_ctxb + (size_t)(grow0 + r) * 256 + q4);
    }
    #pragma unroll
    for (int i = 0; i < 2; i++) {
        int lin = tid + i * 256;
        int kr = lin >> 5, n4 = (lin & 31) * 4;
        cp16(sptr(&s.Bm[0][kr][n4]), g_W1cb + (size_t)(bcol * 16) * 2048 + kr * 128 + n4);
    }
    CP_COMMIT();

    for (int kc = 0; kc < 16; kc++) {
        const int buf = kc & 1;
        if (kc + 1 < 16) {
            #pragma unroll
            for (int i = 0; i < 2; i++) {
                int lin = tid + i * 256;
                int r = lin >> 2, q4 = (lin & 3) * 4;
                cp16(sptr(&s.A[buf ^ 1][r][q4]),
                     g_ctxb + (size_t)(grow0 + r) * 256 + (kc + 1) * 16 + q4);
            }
            #pragma unroll
            for (int i = 0; i < 2; i++) {
                int lin = tid + i * 256;
                int kr = lin >> 5, n4 = (lin & 31) * 4;
                cp16(sptr(&s.Bm[buf ^ 1][kr][n4]),
                     g_W1cb + (size_t)(bcol * 16 + kc + 1) * 2048 + kr * 128 + n4);
            }
            CP_COMMIT();
            asm volatile("cp.async.wait_group 1;" ::: "memory");
        } else {
            asm volatile("cp.async.wait_group 0;" ::: "memory");
        }
        __syncthreads();

        #pragma unroll
        for (int kt = 0; kt < 2; kt++) {
            const int qa = kt * 8 + (lane & 3);
            uint32_t af[2][4];
            #pragma unroll
            for (int mt = 0; mt < 2; mt++) {
                int r = wm * 32 + mt * 16 + (lane >> 2);
                af[mt][0] = s.A[buf][r][qa];
                af[mt][1] = s.A[buf][r + 8][qa];
                af[mt][2] = s.A[buf][r][qa + 4];
                af[mt][3] = s.A[buf][r + 8][qa + 4];
            }
            #pragma unroll
            for (int nt = 0; nt < 8; nt++) {
                int nn = wn * 64 + nt * 8 + (lane >> 2);
                uint32_t b0 = s.Bm[buf][qa][nn];
                uint32_t b1 = s.Bm[buf][qa + 4][nn];
                #pragma unroll
                for (int mt = 0; mt < 2; mt++)
                    MMA_BF16(acc[mt][nt], af[mt], b0, b1);
            }
        }
        __syncthreads();
    }

    // epilogue: + b1, pack bf16, store in step-kernel fragment layout.
    // step thread coords: b = brow*2 + (wm>>1); tid_s = ((wm&1)*2+wn)*32 + (lane>>2)*4 + (lane&3)
    {
        const int b = brow * 2 + (wm >> 1);
        const int tid_s = (((wm & 1) * 2 + wn) << 5) + ((lane >> 2) << 2) + (lane & 3);
        #pragma unroll
        for (int nt = 0; nt < 8; nt++) {
            int c = bcol * 128 + wn * 64 + nt * 8 + 2 * (lane & 3);
            float2 bv = *reinterpret_cast<const float2*>(&b1[c]);
            uint4 v;
            v.x = packbf(acc[0][nt][0] + bv.x, acc[0][nt][1] + bv.y);  // mt0, hf0
            v.y = packbf(acc[0][nt][2] + bv.x, acc[0][nt][3] + bv.y);  // mt0, hf1
            v.z = packbf(acc[1][nt][0] + bv.x, acc[1][nt][1] + bv.y);  // mt1, hf0
            v.w = packbf(acc[1][nt][2] + bv.x, acc[1][nt][3] + bv.y);  // mt1, hf1
            g_ctxpf[(((size_t)b * 4 + bcol) * 8 + nt) * 128 + tid_s] = v;
        }
    }
}

// ================= persistent bf16 step kernel =================
// 64-row CTAs, 2 CTAs/SM. 4 warps (2m x 2n), warp tile 32x64.
struct PS {
    float    zf[64][130];
    uint32_t zb[64][68];
    uint32_t hb[64][68];
    uint32_t wb[4][16][136];
};
#define PS_SZ ((int)sizeof(PS))

extern __shared__ char dynsm[];

__device__ __forceinline__ void mma_slice_zreg(
    float acc[2][8][4], const uint32_t (&af)[2][2][4],
    const uint32_t (&Bm)[16][136], int lane, int wn)
{
    #pragma unroll
    for (int kt = 0; kt < 2; kt++) {
        const int kq = kt * 8 + (lane & 3);
        #pragma unroll
        for (int nt = 0; nt < 8; nt++) {
            int nn = wn * 64 + nt * 8 + (lane >> 2);
            uint32_t b0 = Bm[kq][nn];
            uint32_t b1 = Bm[kq + 4][nn];
            #pragma unroll
            for (int mt = 0; mt < 2; mt++)
                MMA_BF16(acc[mt][nt], af[kt][mt], b0, b1);
        }
    }
}

__device__ __forceinline__ void mma_slice(
    float acc[2][8][4], const uint32_t (&A)[64][68], int qb,
    const uint32_t (&Bm)[16][136], int lane, int wm, int wn)
{
    #pragma unroll
    for (int kt = 0; kt < 2; kt++) {
        const int qa = qb + kt * 8 + (lane & 3);
        uint32_t af[2][4];
        #pragma unroll
        for (int mt = 0; mt < 2; mt++) {
            int r = wm * 32 + mt * 16 + (lane >> 2);
            af[mt][0] = A[r][qa];
            af[mt][1] = A[r + 8][qa];
            af[mt][2] = A[r][qa + 4];
            af[mt][3] = A[r + 8][qa + 4];
        }
        const int kq = kt * 8 + (lane & 3);
        #pragma unroll
        for (int nt = 0; nt < 8; nt++) {
            int nn = wn * 64 + nt * 8 + (lane >> 2);
            uint32_t b0 = Bm[kq][nn];
            uint32_t b1 = Bm[kq + 4][nn];
            #pragma unroll
            for (int mt = 0; mt < 2; mt++)
                MMA_BF16(acc[mt][nt], af[mt], b0, b1);
        }
    }
}

__global__ void __launch_bounds__(128, 2) step_kernel(
    const float* __restrict__ eps0, const float* __restrict__ eps,
    const float* __restrict__ beta, const float* __restrict__ sigma0,
    const float* __restrict__ b2,   const float* __restrict__ temb,
    const float* __restrict__ tmu,  float* __restrict__ out)
{
    PS* s = (PS*)dynsm;
    const int tid = threadIdx.x, lane = tid & 31, w = tid >> 5;
    const int wm = w >> 1, wn = w & 1;
    const int grow0 = blockIdx.x * 64;

    const float s0 = sigma0[0];
    const float lg = logf(s0);
    const float dt = 1.0f / TSTEPS;
    double ssum = 0.0;

    {
        float local = 0.f;
        #pragma unroll
        for (int i = 0; i < 16; i++) {
            int lin = (tid + i * 128) * 4;
            int row = lin >> 7, col = lin & 127;
            float4 e = *reinterpret_cast<const float4*>(&eps0[(size_t)(grow0 + row) * ZD + col]);
            float z0 = s0 * e.x, z1 = s0 * e.y, z2 = s0 * e.z, z3 = s0 * e.w;
            s->zf[row][col + 0] = z0; s->zf[row][col + 1] = z1;
            s->zf[row][col + 2] = z2; s->zf[row][col + 3] = z3;
            s->zb[row][(col >> 1) + 0] = packbf(z0, z1);
            s->zb[row][(col >> 1) + 1] = packbf(z2, z3);
            local += 0.5f * (e.x * e.x + e.y * e.y + e.z * e.z + e.w * e.w) + 4.f * lg;
        }
        ssum += (double)local;
    }

#define ISSUE_GROUP(gv) do { \
    const uint32_t* _src = g_Wsl + (((gv) & 15) * 2) * 2048; \
    const int _slot0 = ((gv) & 1) * 2; \
    _Pragma("unroll") \
    for (int _i = 0; _i < 8; _i++) { \
        int _j = tid + _i * 128; \
        int _sl = _j >> 9, _rem = _j & 511; \
        cp16(sptr(&s->wb[_slot0 + _sl][_rem >> 5][(_rem & 31) * 4]), \
             _src + _sl * 2048 + _rem * 4); \
    } \
    CP_COMMIT(); \
} while (0)

#define GROUP_SYNC() do { \
    asm volatile("cp.async.wait_group 0;" ::: "memory"); \
    __syncthreads(); \
} while (0)

    ISSUE_GROUP(0);

    int g = 0;
    for (int t = 0; t < TSTEPS; t++) {
        const float beta_f = __ldg(&beta[t]);
        const float beta_b = __ldg(&beta[(t + TSTEPS - 1) % TSTEPS]);
        const float sig_f = sqrtf(2.0f * beta_f * dt) * s0;
        const float sig_b = sqrtf(2.0f * beta_b * dt) * s0;
        const float inv_sb = 1.0f / sig_b;
        const float logdiff = logf(sig_f) - logf(sig_b);
        const float* eps_t = eps + ((size_t)t * B_DIM + grow0) * ZD;

        float accu[2][8][4] = {};
        uint32_t za[4][2][2][4];

        #pragma unroll 1
        for (int c = 0; c < 4; c++) {
            float acch[2][8][4] = {};
            #pragma unroll
            for (int half = 0; half < 2; half++) {
                GROUP_SYNC();
                if (c == 0 && half == 0) {
                    #pragma unroll
                    for (int kc = 0; kc < 4; kc++)
                        #pragma unroll
                        for (int kt = 0; kt < 2; kt++) {
                            int qa = kc * 16 + kt * 8 + (lane & 3);
                            #pragma unroll
                            for (int mt = 0; mt < 2; mt++) {
                                int r = wm * 32 + mt * 16 + (lane >> 2);
                                za[kc][kt][mt][0] = s->zb[r][qa];
                                za[kc][kt][mt][1] = s->zb[r + 8][qa];
                                za[kc][kt][mt][2] = s->zb[r][qa + 4];
                                za[kc][kt][mt][3] = s->zb[r + 8][qa + 4];
                            }
                        }
                }
                ISSUE_GROUP(g + 1);
                const int slot0 = (g & 1) * 2;
                mma_slice_zreg(acch, za[half * 2 + 0], s->wb[slot0 + 0], lane, wn);
                mma_slice_zreg(acch, za[half * 2 + 1], s->wb[slot0 + 1], lane, wn);
                g++;
            }
            // ---- epilogue1: h = bf16(relu(acch + ctxp + te)) -> hb ----
            // ctxp in fragment layout: 8 coalesced LDG.128
            uint4 cp4[8];
            {
                const uint4* base = g_ctxpf + (((size_t)blockIdx.x * 4 + c) * 8) * 128 + tid;
                #pragma unroll
                for (int nt = 0; nt < 8; nt++)
                    cp4[nt] = __ldg(base + nt * 128);
            }
            #pragma unroll
            for (int nt = 0; nt < 8; nt++) {
                int gc = c * 128 + wn * 64 + nt * 8 + 2 * (lane & 3);
                float2 te = *reinterpret_cast<const float2*>(&temb[(size_t)t * HD + gc]);
                int lq = wn * 32 + nt * 4 + (lane & 3);
                const uint32_t cpv[2][2] = {
                    { cp4[nt].x, cp4[nt].y },   // mt0: hf0, hf1
                    { cp4[nt].z, cp4[nt].w } }; // mt1: hf0, hf1
                #pragma unroll
                for (int mt = 0; mt < 2; mt++) {
                    int r = wm * 32 + mt * 16 + (lane >> 2);
                    #pragma unroll
                    for (int hf = 0; hf < 2; hf++) {
                        int rr = r + 8 * hf;
                        uint32_t cv = cpv[mt][hf];
                        float v0 = acch[mt][nt][hf * 2 + 0] + bflo(cv) + te.x;
                        float v1 = acch[mt][nt][hf * 2 + 1] + bfhi(cv) + te.y;
                        s->hb[rr][lq] = packbf(fmaxf(v0, 0.f), fmaxf(v1, 0.f));
                    }
                }
            }
            #pragma unroll
            for (int half = 0; half < 2; half++) {
                GROUP_SYNC();
                ISSUE_GROUP(g + 1);
                const int slot0 = (g & 1) * 2;
                mma_slice(accu, s->hb, (half * 2 + 0) * 16, s->wb[slot0 + 0], lane, wm, wn);
                mma_slice(accu, s->hb, (half * 2 + 1) * 16, s->wb[slot0 + 1], lane, wm, wn);
                g++;
            }
        }

        // ---- update epilogue ----
        float local = 0.f;
        #pragma unroll
        for (int nt = 0; nt < 8; nt++) {
            int cc = wn * 64 + nt * 8 + 2 * (lane & 3);
            float2 bv = *reinterpret_cast<const float2*>(&b2[cc]);
            #pragma unroll
            for (int mt = 0; mt < 2; mt++) {
                int r = wm * 32 + mt * 16 + (lane >> 2);
                #pragma unroll
                for (int hf = 0; hf < 2; hf++) {
                    int rr = r + 8 * hf;
                    float2 zp = *reinterpret_cast<const float2*>(&s->zf[rr][cc]);
                    float2 ev = *reinterpret_cast<const float2*>(&eps_t[(size_t)rr * ZD + cc]);
                    float u0 = accu[mt][nt][hf * 2 + 0] + bv.x;
                    float u1 = accu[mt][nt][hf * 2 + 1] + bv.y;
                    float mu0 = zp.x + (beta_f * zp.x + u0) * dt;
                    float mu1 = zp.y + (beta_f * zp.y + u1) * dt;
                    float zn0 = fmaf(sig_f, ev.x, mu0);
                    float zn1 = fmaf(sig_f, ev.y, mu1);
                    float mb0 = zn0 - beta_b * zn0 * dt;
                    float mb1 = zn1 - beta_b * zn1 * dt;
                    float a10 = (zp.x - mb0) * inv_sb;
                    float a11 = (zp.y - mb1) * inv_sb;
                    local += 0.5f * (ev.x * ev.x - a10 * a10) + logdiff;
                    local += 0.5f * (ev.y * ev.y - a11 * a11) + logdiff;
                    if (t == TSTEPS - 1) {
                        float2 tm = *reinterpret_cast<const float2*>(
                            &tmu[(size_t)(grow0 + rr) * ZD + cc]);
                        float d0 = zn0 - tm.x, d1 = zn1 - tm.y;
                        local -= 0.5f * (d0 * d0 + d1 * d1);
                    }
                    float2 zo = { zn0, zn1 };
                    *reinterpret_cast<float2*>(&s->zf[rr][cc]) = zo;
                    s->zb[rr][cc >> 1] = packbf(zn0, zn1);
                }
            }
        }
        ssum += (double)local;
    }

    // ---- reduce + fused output ----
    asm volatile("cp.async.wait_group 0;" ::: "memory");
    __syncthreads();
    double* red = reinterpret_cast<double*>(&s->wb[0][0][0]);
    red[tid] = ssum;
    __syncthreads();
    for (int st = 64; st > 0; st >>= 1) {
        if (tid < st) red[tid] += red[tid + st];
        __syncthreads();
    }
    if (tid == 0) {
        atomicAdd(&g_sum, red[0]);
        __threadfence();
        int done = atomicAdd(&g_done, 1);
        if (done == (int)gridDim.x - 1) {
            double total = atomicAdd(&g_sum, 0.0);
            out[0] = (float)(total / (double)B_DIM);
            g_done = 0;
        }
    }
}

// ---------------- host launcher ----------------
extern "C" void kernel_launch(void* const* d_in, const int* in_sizes, int n_in,
                              void* d_out, int out_size)
{
    (void)in_sizes; (void)n_in; (void)out_size;
    const float* ctx    = (const float*)d_in[0];
    const float* eps0   = (const float*)d_in[1];
    const float* eps    = (const float*)d_in[2];
    const float* beta   = (const float*)d_in[3];
    const float* sigma0 = (const float*)d_in[4];
    const float* W1     = (const float*)d_in[5];
    const float* b1     = (const float*)d_in[6];
    const float* W2     = (const float*)d_in[7];
    const float* b2     = (const float*)d_in[8];
    const float* temb   = (const float*)d_in[9];
    const float* tmu    = (const float*)d_in[10];
    float* out = (float*)d_out;

    cudaFuncSetAttribute(step_kernel, cudaFuncAttributeMaxDynamicSharedMemorySize, PS_SZ);

    prep_all<<<B_DIM, 256>>>(ctx, W1, W2);
    ctxproj_bf16<<<dim3(4, 128), 256>>>(b1);
    step_kernel<<<256, 128, PS_SZ>>>(eps0, eps, beta, sigma0, b2, temb, tmu, out);
}

// round 17
// speedup vs baseline: 1.3127x; 1.0173x over previous
#include <cuda_runtime.h>
#include <cstdint>
#include <math.h>

#define B_DIM  16384
#define ZD     128
#define HD     512
#define TSTEPS 32

// ---------------- device global scratch ----------------
__device__ __align__(16) uint32_t g_ctxb[(size_t)B_DIM * 256]; // ctx packed bf16x2 pairs
__device__ __align__(16) uint32_t g_W1cb[64 * 2048];           // W1[128:640,:] bf16 slices [16q][128n]
__device__ __align__(16) uint4    g_ctxpf[256 * 4 * 8 * 128];  // ctxproj, step-fragment layout
__device__ __align__(16) uint32_t g_Wsl[32 * 2048];            // 32 loop weight slices [16q][128n]
__device__ double g_sum;
__device__ int    g_done;

// ---------------- helpers ----------------
__device__ __forceinline__ uint32_t packbf(float lo, float hi) {
    uint32_t r; asm("cvt.rn.bf16x2.f32 %0, %1, %2;" : "=r"(r) : "f"(hi), "f"(lo)); return r;
}
__device__ __forceinline__ float bflo(uint32_t u) { return __uint_as_float(u << 16); }
__device__ __forceinline__ float bfhi(uint32_t u) { return __uint_as_float(u & 0xFFFF0000u); }
__device__ __forceinline__ uint32_t sptr(const void* p) {
    return (uint32_t)__cvta_generic_to_shared(p);
}
__device__ __forceinline__ void cp16(uint32_t d, const void* s) {
    asm volatile("cp.async.cg.shared.global [%0], [%1], 16;" :: "r"(d), "l"(s));
}
#define CP_COMMIT() asm volatile("cp.async.commit_group;" ::: "memory")

#define MMA_BF16(acc, af, b0, b1) \
    asm volatile("mma.sync.aligned.m16n8k16.row.col.f32.bf16.bf16.f32 " \
        "{%0,%1,%2,%3}, {%4,%5,%6,%7}, {%8,%9}, {%0,%1,%2,%3};" \
        : "+f"((acc)[0]), "+f"((acc)[1]), "+f"((acc)[2]), "+f"((acc)[3]) \
        : "r"((af)[0]), "r"((af)[1]), "r"((af)[2]), "r"((af)[3]), \
          "r"(b0), "r"(b1))

// ================= fused prep =================
__global__ void prep_all(const float* __restrict__ ctx,
                         const float* __restrict__ W1,
                         const float* __restrict__ W2)
{
    int idx = blockIdx.x * 256 + threadIdx.x;
    if (idx == 0) g_sum = 0.0;

    if (idx < B_DIM * 256) {
        int row = idx >> 8, q = idx & 255;
        float v0 = ctx[(size_t)row * HD + 2 * q];
        float v1 = ctx[(size_t)row * HD + 2 * q + 1];
        g_ctxb[idx] = packbf(v0, v1);
    }
    if (idx < 64 * 2048) {
        int si = idx >> 11, rem = idx & 2047;
        int q = rem >> 7, n = rem & 127;
        int c = si >> 4, kc = si & 15;
        int k0 = ZD + kc * 32 + 2 * q;
        float v0 = W1[(size_t)k0 * HD + c * 128 + n];
        float v1 = W1[(size_t)(k0 + 1) * HD + c * 128 + n];
        g_W1cb[idx] = packbf(v0, v1);
    }
    if (idx < 32 * 2048) {
        int si = idx >> 11, rem = idx & 2047;
        int q = rem >> 7, n = rem & 127;
        int c = si >> 3, ph = (si >> 2) & 1, kc = si & 3;
        float v0, v1;
        if (!ph) {
            int k0 = kc * 32 + 2 * q;
            v0 = W1[(size_t)k0 * HD + c * 128 + n];
            v1 = W1[(size_t)(k0 + 1) * HD + c * 128 + n];
        } else {
            int k0 = c * 128 + kc * 32 + 2 * q;
            v0 = W2[(size_t)k0 * ZD + n];
            v1 = W2[(size_t)(k0 + 1) * ZD + n];
        }
        g_Wsl[idx] = packbf(v0, v1);
    }
}

// ================= bf16 ctxproj (unchanged from 629us best) =================
struct CS {
    uint32_t A[2][128][20];
    uint32_t Bm[2][16][136];
};

__global__ void __launch_bounds__(256, 2) ctxproj_bf16(const float* __restrict__ b1)
{
    __shared__ CS s;
    const int tid = threadIdx.x, lane = tid & 31, w = tid >> 5;
    const int wm = w >> 1, wn = w & 1;
    const int bcol = blockIdx.x, brow = blockIdx.y;
    const int grow0 = brow * 128;

    float acc[2][8][4] = {};

    #pragma unroll
    for (int i = 0; i < 2; i++) {
        int lin = tid + i * 256;
        int r = lin >> 2, q4 = (lin & 3) * 4;
        cp16(sptr(&s.A[0][r][q4]), g_ctxb + (size_t)(grow0 + r) * 256 + q4);
    }
    #pragma unroll
    for (int i = 0; i < 2; i++) {
        int lin = tid + i * 256;
        int kr = lin >> 5, n4 = (lin & 31) * 4;
        cp16(sptr(&s.Bm[0][kr][n4]), g_W1cb + (size_t)(bcol * 16) * 2048 + kr * 128 + n4);
    }
    CP_COMMIT();

    for (int kc = 0; kc < 16; kc++) {
        const int buf = kc & 1;
        if (kc + 1 < 16) {
            #pragma unroll
            for (int i = 0; i < 2; i++) {
                int lin = tid + i * 256;
                int r = lin >> 2, q4 = (lin & 3) * 4;
                cp16(sptr(&s.A[buf ^ 1][r][q4]),
                     g_ctxb + (size_t)(grow0 + r) * 256 + (kc + 1) * 16 + q4);
            }
            #pragma unroll
            for (int i = 0; i < 2; i++) {
                int lin = tid + i * 256;
                int kr = lin >> 5, n4 = (lin & 31) * 4;
                cp16(sptr(&s.Bm[buf ^ 1][kr][n4]),
                     g_W1cb + (size_t)(bcol * 16 + kc + 1) * 2048 + kr * 128 + n4);
            }
            CP_COMMIT();
            asm volatile("cp.async.wait_group 1;" ::: "memory");
        } else {
            asm volatile("cp.async.wait_group 0;" ::: "memory");
        }
        __syncthreads();

        #pragma unroll
        for (int kt = 0; kt < 2; kt++) {
            const int qa = kt * 8 + (lane & 3);
            uint32_t af[2][4];
            #pragma unroll
            for (int mt = 0; mt < 2; mt++) {
                int r = wm * 32 + mt * 16 + (lane >> 2);
                af[mt][0] = s.A[buf][r][qa];
                af[mt][1] = s.A[buf][r + 8][qa];
                af[mt][2] = s.A[buf][r][qa + 4];
                af[mt][3] = s.A[buf][r + 8][qa + 4];
            }
            #pragma unroll
            for (int nt = 0; nt < 8; nt++) {
                int nn = wn * 64 + nt * 8 + (lane >> 2);
                uint32_t b0 = s.Bm[buf][qa][nn];
                uint32_t b1 = s.Bm[buf][qa + 4][nn];
                #pragma unroll
                for (int mt = 0; mt < 2; mt++)
                    MMA_BF16(acc[mt][nt], af[mt], b0, b1);
            }
        }
        __syncthreads();
    }

    {
        const int b = brow * 2 + (wm >> 1);
        const int tid_s = (((wm & 1) * 2 + wn) << 5) + ((lane >> 2) << 2) + (lane & 3);
        #pragma unroll
        for (int nt = 0; nt < 8; nt++) {
            int c = bcol * 128 + wn * 64 + nt * 8 + 2 * (lane & 3);
            float2 bv = *reinterpret_cast<const float2*>(&b1[c]);
            uint4 v;
            v.x = packbf(acc[0][nt][0] + bv.x, acc[0][nt][1] + bv.y);
            v.y = packbf(acc[0][nt][2] + bv.x, acc[0][nt][3] + bv.y);
            v.z = packbf(acc[1][nt][0] + bv.x, acc[1][nt][1] + bv.y);
            v.w = packbf(acc[1][nt][2] + bv.x, acc[1][nt][3] + bv.y);
            g_ctxpf[(((size_t)b * 4 + bcol) * 8 + nt) * 128 + tid_s] = v;
        }
    }
}

// ================= persistent bf16 step kernel =================
// 64-row CTAs, 2 CTAs/SM. 4 warps (2m x 2n), warp tile 32x64.
// z fp32 state in registers (fragment-owned); eps staged via cp.async into eb.
struct PS {
    float    eb[64][132];     // eps staging (528B/row, 16B-aligned)  33792 B
    uint32_t zb[64][68];      // bf16x2 z pairs                       17408 B
    uint32_t hb[64][68];      // bf16x2 h chunk pairs                 17408 B
    uint32_t wb[4][16][136];  // weight slice ring                    34816 B
};
#define PS_SZ ((int)sizeof(PS))

extern __shared__ char dynsm[];

__device__ __forceinline__ void mma_slice_zreg(
    float acc[2][8][4], const uint32_t (&af)[2][2][4],
    const uint32_t (&Bm)[16][136], int lane, int wn)
{
    #pragma unroll
    for (int kt = 0; kt < 2; kt++) {
        const int kq = kt * 8 + (lane & 3);
        #pragma unroll
        for (int nt = 0; nt < 8; nt++) {
            int nn = wn * 64 + nt * 8 + (lane >> 2);
            uint32_t b0 = Bm[kq][nn];
            uint32_t b1 = Bm[kq + 4][nn];
            #pragma unroll
            for (int mt = 0; mt < 2; mt++)
                MMA_BF16(acc[mt][nt], af[kt][mt], b0, b1);
        }
    }
}

__device__ __forceinline__ void mma_slice(
    float acc[2][8][4], const uint32_t (&A)[64][68], int qb,
    const uint32_t (&Bm)[16][136], int lane, int wm, int wn)
{
    #pragma unroll
    for (int kt = 0; kt < 2; kt++) {
        const int qa = qb + kt * 8 + (lane & 3);
        uint32_t af[2][4];
        #pragma unroll
        for (int mt = 0; mt < 2; mt++) {
            int r = wm * 32 + mt * 16 + (lane >> 2);
            af[mt][0] = A[r][qa];
            af[mt][1] = A[r + 8][qa];
            af[mt][2] = A[r][qa + 4];
            af[mt][3] = A[r + 8][qa + 4];
        }
        const int kq = kt * 8 + (lane & 3);
        #pragma unroll
        for (int nt = 0; nt < 8; nt++) {
            int nn = wn * 64 + nt * 8 + (lane >> 2);
            uint32_t b0 = Bm[kq][nn];
            uint32_t b1 = Bm[kq + 4][nn];
            #pragma unroll
            for (int mt = 0; mt < 2; mt++)
                MMA_BF16(acc[mt][nt], af[mt], b0, b1);
        }
    }
}

__global__ void __launch_bounds__(128, 2) step_kernel(
    const float* __restrict__ eps0, const float* __restrict__ eps,
    const float* __restrict__ beta, const float* __restrict__ sigma0,
    const float* __restrict__ b2,   const float* __restrict__ temb,
    const float* __restrict__ tmu,  float* __restrict__ out)
{
    PS* s = (PS*)dynsm;
    const int tid = threadIdx.x, lane = tid & 31, w = tid >> 5;
    const int wm = w >> 1, wn = w & 1;
    const int grow0 = blockIdx.x * 64;

    const float s0 = sigma0[0];
    const float lg = logf(s0);
    const float dt = 1.0f / TSTEPS;
    double ssum = 0.0;

    // ---- init: z fp32 in registers (fragment-owned) + zb smem + prior term ----
    float2 zst[8][2][2];
    {
        float local = 0.f;
        #pragma unroll
        for (int nt = 0; nt < 8; nt++) {
            int cc = wn * 64 + nt * 8 + 2 * (lane & 3);
            #pragma unroll
            for (int mt = 0; mt < 2; mt++) {
                int r = wm * 32 + mt * 16 + (lane >> 2);
                #pragma unroll
                for (int hf = 0; hf < 2; hf++) {
                    int rr = r + 8 * hf;
                    float2 e = *reinterpret_cast<const float2*>(
                        &eps0[(size_t)(grow0 + rr) * ZD + cc]);
                    float2 z = { s0 * e.x, s0 * e.y };
                    zst[nt][mt][hf] = z;
                    s->zb[rr][cc >> 1] = packbf(z.x, z.y);
                    local += 0.5f * (e.x * e.x + e.y * e.y) + 2.f * lg;
                }
            }
        }
        ssum += (double)local;
    }

#define ISSUE_GROUP(gv) do { \
    const uint32_t* _src = g_Wsl + (((gv) & 15) * 2) * 2048; \
    const int _slot0 = ((gv) & 1) * 2; \
    _Pragma("unroll") \
    for (int _i = 0; _i < 8; _i++) { \
        int _j = tid + _i * 128; \
        int _sl = _j >> 9, _rem = _j & 511; \
        cp16(sptr(&s->wb[_slot0 + _sl][_rem >> 5][(_rem & 31) * 4]), \
             _src + _sl * 2048 + _rem * 4); \
    } \
    CP_COMMIT(); \
} while (0)

#define GROUP_SYNC() do { \
    asm volatile("cp.async.wait_group 0;" ::: "memory"); \
    __syncthreads(); \
} while (0)

    ISSUE_GROUP(0);

    int g = 0;
    for (int t = 0; t < TSTEPS; t++) {
        const float beta_f = __ldg(&beta[t]);
        const float beta_b = __ldg(&beta[(t + TSTEPS - 1) % TSTEPS]);
        const float sig_f = sqrtf(2.0f * beta_f * dt) * s0;
        const float sig_b = sqrtf(2.0f * beta_b * dt) * s0;
        const float inv_sb = 1.0f / sig_b;
        const float logdiff = logf(sig_f) - logf(sig_b);
        const float* eps_t = eps + ((size_t)t * B_DIM + grow0) * ZD;

        float accu[2][8][4] = {};
        uint32_t za[4][2][2][4];

        #pragma unroll 1
        for (int c = 0; c < 4; c++) {
            float acch[2][8][4] = {};
            #pragma unroll
            for (int half = 0; half < 2; half++) {
                GROUP_SYNC();
                if (c == 0 && half == 0) {
                    // z fragments for the whole step
                    #pragma unroll
                    for (int kc = 0; kc < 4; kc++)
                        #pragma unroll
                        for (int kt = 0; kt < 2; kt++) {
                            int qa = kc * 16 + kt * 8 + (lane & 3);
                            #pragma unroll
                            for (int mt = 0; mt < 2; mt++) {
                                int r = wm * 32 + mt * 16 + (lane >> 2);
                                za[kc][kt][mt][0] = s->zb[r][qa];
                                za[kc][kt][mt][1] = s->zb[r + 8][qa];
                                za[kc][kt][mt][2] = s->zb[r][qa + 4];
                                za[kc][kt][mt][3] = s->zb[r + 8][qa + 4];
                            }
                        }
                    // stage eps(t): 2048 cp16 = 64 rows x 128 floats
                    #pragma unroll
                    for (int i = 0; i < 16; i++) {
                        int lin = tid + i * 128;
                        int row = lin >> 5, col4 = (lin & 31) * 4;
                        cp16(sptr(&s->eb[row][col4]), eps_t + (size_t)row * ZD + col4);
                    }
                }
                ISSUE_GROUP(g + 1);
                const int slot0 = (g & 1) * 2;
                mma_slice_zreg(acch, za[half * 2 + 0], s->wb[slot0 + 0], lane, wn);
                mma_slice_zreg(acch, za[half * 2 + 1], s->wb[slot0 + 1], lane, wn);
                g++;
            }
            // ---- epilogue1: h = bf16(relu(acch + ctxp + te)) -> hb ----
            uint4 cp4[8];
            {
                const uint4* base = g_ctxpf + (((size_t)blockIdx.x * 4 + c) * 8) * 128 + tid;
                #pragma unroll
                for (int nt = 0; nt < 8; nt++)
                    cp4[nt] = __ldg(base + nt * 128);
            }
            #pragma unroll
            for (int nt = 0; nt < 8; nt++) {
                int gc = c * 128 + wn * 64 + nt * 8 + 2 * (lane & 3);
                float2 te = *reinterpret_cast<const float2*>(&temb[(size_t)t * HD + gc]);
                int lq = wn * 32 + nt * 4 + (lane & 3);
                const uint32_t cpv[2][2] = {
                    { cp4[nt].x, cp4[nt].y },
                    { cp4[nt].z, cp4[nt].w } };
                #pragma unroll
                for (int mt = 0; mt < 2; mt++) {
                    int r = wm * 32 + mt * 16 + (lane >> 2);
                    #pragma unroll
                    for (int hf = 0; hf < 2; hf++) {
                        int rr = r + 8 * hf;
                        uint32_t cv = cpv[mt][hf];
                        float v0 = acch[mt][nt][hf * 2 + 0] + bflo(cv) + te.x;
                        float v1 = acch[mt][nt][hf * 2 + 1] + bfhi(cv) + te.y;
                        s->hb[rr][lq] = packbf(fmaxf(v0, 0.f), fmaxf(v1, 0.f));
                    }
                }
            }
            #pragma unroll
            for (int half = 0; half < 2; half++) {
                GROUP_SYNC();
                ISSUE_GROUP(g + 1);
                const int slot0 = (g & 1) * 2;
                mma_slice(accu, s->hb, (half * 2 + 0) * 16, s->wb[slot0 + 0], lane, wm, wn);
                mma_slice(accu, s->hb, (half * 2 + 1) * 16, s->wb[slot0 + 1], lane, wm, wn);
                g++;
            }
        }

        // ---- update epilogue (z in registers, eps from smem) ----
        float local = 0.f;
        #pragma unroll
        for (int nt = 0; nt < 8; nt++) {
            int cc = wn * 64 + nt * 8 + 2 * (lane & 3);
            float2 bv = *reinterpret_cast<const float2*>(&b2[cc]);
            #pragma unroll
            for (int mt = 0; mt < 2; mt++) {
                int r = wm * 32 + mt * 16 + (lane >> 2);
                #pragma unroll
                for (int hf = 0; hf < 2; hf++) {
                    int rr = r + 8 * hf;
                    float2 zp = zst[nt][mt][hf];
                    float2 ev = *reinterpret_cast<const float2*>(&s->eb[rr][cc]);
                    float u0 = accu[mt][nt][hf * 2 + 0] + bv.x;
                    float u1 = accu[mt][nt][hf * 2 + 1] + bv.y;
                    float mu0 = zp.x + (beta_f * zp.x + u0) * dt;
                    float mu1 = zp.y + (beta_f * zp.y + u1) * dt;
                    float zn0 = fmaf(sig_f, ev.x, mu0);
                    float zn1 = fmaf(sig_f, ev.y, mu1);
                    float mb0 = zn0 - beta_b * zn0 * dt;
                    float mb1 = zn1 - beta_b * zn1 * dt;
                    float a10 = (zp.x - mb0) * inv_sb;
                    float a11 = (zp.y - mb1) * inv_sb;
                    local += 0.5f * (ev.x * ev.x - a10 * a10) + logdiff;
                    local += 0.5f * (ev.y * ev.y - a11 * a11) + logdiff;
                    if (t == TSTEPS - 1) {
                        float2 tm = *reinterpret_cast<const float2*>(
                            &tmu[(size_t)(grow0 + rr) * ZD + cc]);
                        float d0 = zn0 - tm.x, d1 = zn1 - tm.y;
                        local -= 0.5f * (d0 * d0 + d1 * d1);
                    }
                    zst[nt][mt][hf] = make_float2(zn0, zn1);
                    s->zb[rr][cc >> 1] = packbf(zn0, zn1);
                }
            }
        }
        ssum += (double)local;
    }

    // ---- reduce + fused output ----
    asm volatile("cp.async.wait_group 0;" ::: "memory");
    __syncthreads();
    double* red = reinterpret_cast<double*>(&s->wb[0][0][0]);
    red[tid] = ssum;
    __syncthreads();
    for (int st = 64; st > 0; st >>= 1) {
        if (tid < st) red[tid] += red[tid + st];
        __syncthreads();
    }
    if (tid == 0) {
        atomicAdd(&g_sum, red[0]);
        __threadfence();
        int done = atomicAdd(&g_done, 1);
        if (done == (int)gridDim.x - 1) {
            double total = atomicAdd(&g_sum, 0.0);
            out[0] = (float)(total / (double)B_DIM);
            g_done = 0;
        }
    }
}

// ---------------- host launcher ----------------
extern "C" void kernel_launch(void* const* d_in, const int* in_sizes, int n_in,
                              void* d_out, int out_size)
{
    (void)in_sizes; (void)n_in; (void)out_size;
    const float* ctx    = (const float*)d_in[0];
    const float* eps0   = (const float*)d_in[1];
    const float* eps    = (const float*)d_in[2];
    const float* beta   = (const float*)d_in[3];
    const float* sigma0 = (const float*)d_in[4];
    const float* W1     = (const float*)d_in[5];
    const float* b1     = (const float*)d_in[6];
    const float* W2     = (const float*)d_in[7];
    const float* b2     = (const float*)d_in[8];
    const float* temb   = (const float*)d_in[9];
    const float* tmu    = (const float*)d_in[10];
    float* out = (float*)d_out;

    cudaFuncSetAttribute(step_kernel, cudaFuncAttributeMaxDynamicSharedMemorySize, PS_SZ);

    prep_all<<<B_DIM, 256>>>(ctx, W1, W2);
    ctxproj_bf16<<<dim3(4, 128), 256>>>(b1);
    step_kernel<<<256, 128, PS_SZ>>>(eps0, eps, beta, sigma0, b2, temb, tmu, out);
}